// round 1
// baseline (speedup 1.0000x reference)
#include <cuda_runtime.h>

typedef unsigned long long ull;

#define B_ 4
#define H_ 8
#define L_ 8192
#define D_ 64
#define M_ 256
#define BH_ (B_*H_)
#define TL 64
#define CH 32
#define ROWS_PER_CHUNK (L_/CH)               // 256
#define TILES_PER_CHUNK (ROWS_PER_CHUNK/TL)  // 4
#define NORMV 0.35355339059327373f           // 64^(-1/4)
#define EPSK 1e-6f
#define EPSZ 1e-6f

#define PSTRIDE 258     // Psm row stride (even -> 8B aligned float2 loads)
#define QPSTRIDE 260    // qp row stride
#define ASTRIDE 68      // data tile row stride
#define KVSTRIDE 64

#define PART_SZ (M_*D_ + M_)   // 16640 floats per partial

// scratch (no cudaMalloc allowed): ~68MB partials + 2MB kv + 32KB ksum
__device__ __align__(16) float g_part[BH_*CH*PART_SZ];
__device__ __align__(16) float g_kv[BH_*M_*D_];
__device__ __align__(16) float g_ksum[BH_*M_];

// ---- packed fp32x2 helpers (Blackwell-only FFMA2 path) ----
__device__ __forceinline__ ull pk2(float lo, float hi) {
    ull r; asm("mov.b64 %0, {%1,%2};" : "=l"(r) : "f"(lo), "f"(hi)); return r;
}
__device__ __forceinline__ ull f2m(ull a, ull b, ull c) {
    ull d; asm("fma.rn.f32x2 %0, %1, %2, %3;" : "=l"(d) : "l"(a), "l"(b), "l"(c)); return d;
}
__device__ __forceinline__ float2 up2(ull v) {
    float lo, hi; asm("mov.b64 {%0,%1}, %2;" : "=f"(lo), "=f"(hi) : "l"(v));
    return make_float2(lo, hi);
}

// Load P [256 m][64 d] global -> Psm[d][m] transposed in smem
__device__ __forceinline__ void load_P(float* Psm, const float* __restrict__ Pg, int t) {
    const float4* g4 = (const float4*)Pg;
#pragma unroll
    for (int it = 0; it < 16; it++) {             // 4096 float4 / 256 threads
        int id = t + it * 256;
        int m = id >> 4, c4 = id & 15;
        float4 v = g4[id];
        Psm[(c4*4+0)*PSTRIDE + m] = v.x;
        Psm[(c4*4+1)*PSTRIDE + m] = v.y;
        Psm[(c4*4+2)*PSTRIDE + m] = v.z;
        Psm[(c4*4+3)*PSTRIDE + m] = v.w;
    }
}

// Load 64x64 fp32 tile (scaled) global -> At [64][ASTRIDE]
__device__ __forceinline__ void load_tile64(float* At, const float* __restrict__ g,
                                            float scale, int t) {
    const float4* g4 = (const float4*)g;
#pragma unroll
    for (int it = 0; it < 4; it++) {              // 1024 float4 / 256 threads
        int id = t + it * 256;
        int r = id >> 4, c4 = id & 15;
        float4 v = g4[id];
        v.x *= scale; v.y *= scale; v.z *= scale; v.w *= scale;
        *(float4*)(At + r*ASTRIDE + c4*4) = v;
    }
}

// sqn[r] = 0.5 * sum_d At[r][d]^2   (At already normalized)
__device__ __forceinline__ void compute_sqn(const float* At, float* sqn, int t) {
    if (t < TL) {
        const float* row = At + t * ASTRIDE;
        float s = 0.f;
#pragma unroll
        for (int kk = 0; kk < D_; kk++) { float a = row[kk]; s += a * a; }
        sqn[t] = 0.5f * s;
    }
}

// qp[64 l][256 m] = exp( At[64 l][64 d] @ Psm[64 d][256 m] - sqn[l] + EPSK )
// thread (t>>4) owns 4 l-rows, (t&15) owns 16 m-cols -> 64 outputs
__device__ __forceinline__ void project_tile(const float* __restrict__ Psm,
                                             const float* __restrict__ At,
                                             const float* __restrict__ sqn,
                                             float* __restrict__ qp, int t) {
    const int lg = t >> 4;
    const int mg = t & 15;
    ull acc[4][8];
#pragma unroll
    for (int i = 0; i < 4; i++)
#pragma unroll
        for (int j = 0; j < 8; j++) acc[i][j] = 0ULL;

    for (int kk = 0; kk < D_; kk += 4) {
        float4 av[4];
#pragma unroll
        for (int i = 0; i < 4; i++)
            av[i] = *(const float4*)(At + (lg*4+i)*ASTRIDE + kk);
#pragma unroll
        for (int s = 0; s < 4; s++) {
            const float2* brow = (const float2*)(Psm + (kk+s)*PSTRIDE + mg*16);
            ull b[8];
#pragma unroll
            for (int j = 0; j < 8; j++) { float2 bv = brow[j]; b[j] = pk2(bv.x, bv.y); }
            ull a2[4];
#pragma unroll
            for (int i = 0; i < 4; i++) {
                float c = (s==0)?av[i].x:(s==1)?av[i].y:(s==2)?av[i].z:av[i].w;
                a2[i] = pk2(c, c);
            }
#pragma unroll
            for (int i = 0; i < 4; i++)
#pragma unroll
                for (int j = 0; j < 8; j++)
                    acc[i][j] = f2m(a2[i], b[j], acc[i][j]);
        }
    }
#pragma unroll
    for (int i = 0; i < 4; i++) {
        float s = sqn[lg*4+i];
        float2* orow = (float2*)(qp + (lg*4+i)*QPSTRIDE + mg*16);
#pragma unroll
        for (int j = 0; j < 8; j++) {
            float2 v = up2(acc[i][j]);
            orow[j] = make_float2(__expf(v.x - s + EPSK), __expf(v.y - s + EPSK));
        }
    }
}

#define SMEM1_FLOATS (64*PSTRIDE + 64*QPSTRIDE + 64*ASTRIDE + 64)
#define SMEM1_BYTES  (SMEM1_FLOATS*4)
#define SMEM2_FLOATS (64*PSTRIDE + 64*QPSTRIDE + 64*ASTRIDE + 64 + M_ + 64)
#define SMEM2_BYTES  (SMEM2_FLOATS*4)

// Kernel 1: per (bh, chunk) compute partial kv[256][64] and k_sum[256]
__global__ void __launch_bounds__(256, 1)
k1_kv(const float* __restrict__ kg, const float* __restrict__ vg,
      const float* __restrict__ Pg) {
    extern __shared__ float smem[];
    float* Psm = smem;
    float* qp  = Psm + 64*PSTRIDE;
    float* At  = qp  + 64*QPSTRIDE;
    float* sqn = At  + 64*ASTRIDE;

    const int t = threadIdx.x;
    const int bh = blockIdx.x / CH;
    const int chunk = blockIdx.x % CH;

    load_P(Psm, Pg, t);

    const int mg = t >> 2;   // 4 m-rows:  mg*4..mg*4+3
    const int dg = t & 3;    // 16 d-cols: dg*16..dg*16+15
    ull kvacc[4][8];
    float ksacc[4];
#pragma unroll
    for (int i = 0; i < 4; i++) {
        ksacc[i] = 0.f;
#pragma unroll
        for (int j = 0; j < 8; j++) kvacc[i][j] = 0ULL;
    }

    const size_t gbase = (size_t)bh * L_ * D_;

    for (int tile = 0; tile < TILES_PER_CHUNK; tile++) {
        const int l0 = chunk * ROWS_PER_CHUNK + tile * TL;
        __syncthreads();                       // prev iter consumers done
        load_tile64(At, kg + gbase + (size_t)l0*D_, NORMV, t);
        __syncthreads();
        compute_sqn(At, sqn, t);
        __syncthreads();
        project_tile(Psm, At, sqn, qp, t);     // qp = k'
        __syncthreads();
        load_tile64(At, vg + gbase + (size_t)l0*D_, 1.0f, t);
        __syncthreads();
        // kv += k'^T @ v ; ksum += col-sums of k'
        for (int kk = 0; kk < TL; kk++) {
            float4 a4 = *(const float4*)(qp + kk*QPSTRIDE + mg*4);
            if (dg == 0) {
                ksacc[0] += a4.x; ksacc[1] += a4.y;
                ksacc[2] += a4.z; ksacc[3] += a4.w;
            }
            ull a2[4] = {pk2(a4.x,a4.x), pk2(a4.y,a4.y), pk2(a4.z,a4.z), pk2(a4.w,a4.w)};
            const float2* vr = (const float2*)(At + kk*ASTRIDE + dg*16);
#pragma unroll
            for (int j = 0; j < 8; j++) {
                float2 bv = vr[j];
                ull b = pk2(bv.x, bv.y);
#pragma unroll
                for (int i = 0; i < 4; i++)
                    kvacc[i][j] = f2m(a2[i], b, kvacc[i][j]);
            }
        }
    }
    // write partials (deterministic split-K, no atomics)
    float* pb = g_part + (size_t)(bh*CH + chunk) * PART_SZ;
#pragma unroll
    for (int i = 0; i < 4; i++)
#pragma unroll
        for (int j = 0; j < 8; j++) {
            float2 v = up2(kvacc[i][j]);
            *(float2*)(pb + (mg*4+i)*D_ + dg*16 + j*2) = v;
        }
    if (dg == 0) {
#pragma unroll
        for (int i = 0; i < 4; i++) pb[M_*D_ + mg*4+i] = ksacc[i];
    }
}

// Kernel R: reduce CH partials -> g_kv, g_ksum
__global__ void k_reduce() {
    int idx = blockIdx.x * 256 + threadIdx.x;   // exact: 32*16640/256 = 2080 blocks
    int bh = idx / PART_SZ;
    int r  = idx - bh * PART_SZ;
    const float* p = g_part + (size_t)bh * CH * PART_SZ + r;
    float s = 0.f;
#pragma unroll
    for (int c = 0; c < CH; c++) s += p[(size_t)c * PART_SZ];
    if (r < M_*D_) g_kv[bh*M_*D_ + r] = s;
    else           g_ksum[bh*M_ + (r - M_*D_)] = s;
}

// Kernel 2: per (bh, l-tile) q' projection + out = (q' @ kv) * z
__global__ void __launch_bounds__(256, 1)
k2_out(const float* __restrict__ qg, const float* __restrict__ Pg,
       float* __restrict__ outg) {
    extern __shared__ float smem[];
    float* buf0 = smem;                    // P during projection, then kv
    float* qp   = buf0 + 64*PSTRIDE;
    float* At   = qp   + 64*QPSTRIDE;
    float* sqn  = At   + 64*ASTRIDE;
    float* ksum = sqn  + 64;
    float* zsm  = ksum + M_;

    const int t = threadIdx.x;
    const int bh = blockIdx.x >> 7;
    const int tile = blockIdx.x & 127;
    const int l0 = tile * TL;
    const size_t gbase = (size_t)bh * L_ * D_;

    load_P(buf0, Pg, t);
    load_tile64(At, qg + gbase + (size_t)l0*D_, NORMV, t);
    __syncthreads();
    compute_sqn(At, sqn, t);
    __syncthreads();
    project_tile(buf0, At, sqn, qp, t);    // qp = q'
    __syncthreads();
    // overwrite P buffer with kv [256][64]; load ksum
    {
        const float4* kv4 = (const float4*)(g_kv + (size_t)bh * M_ * D_);
        float4* b4 = (float4*)buf0;
#pragma unroll
        for (int it = 0; it < 16; it++) b4[t + it*256] = kv4[t + it*256];
        ksum[t] = g_ksum[bh*M_ + t];
    }
    __syncthreads();

    const int lg = t >> 4;   // 4 l-rows
    const int dq = t & 15;   // 4 d-cols: dq*4..dq*4+3
    ull oacc[4][2];
    float zacc[4] = {0.f, 0.f, 0.f, 0.f};
#pragma unroll
    for (int i = 0; i < 4; i++) { oacc[i][0] = 0ULL; oacc[i][1] = 0ULL; }

    for (int kk = 0; kk < M_; kk += 4) {
        float4 a4[4];
#pragma unroll
        for (int i = 0; i < 4; i++)
            a4[i] = *(const float4*)(qp + (lg*4+i)*QPSTRIDE + kk);
        float4 ks4 = *(const float4*)(ksum + kk);
        if (dq == 0) {
#pragma unroll
            for (int i = 0; i < 4; i++)
                zacc[i] += a4[i].x*ks4.x + a4[i].y*ks4.y + a4[i].z*ks4.z + a4[i].w*ks4.w;
        }
#pragma unroll
        for (int s = 0; s < 4; s++) {
            const float2* kvr = (const float2*)(buf0 + (kk+s)*KVSTRIDE + dq*4);
            float2 b0f = kvr[0], b1f = kvr[1];
            ull b0 = pk2(b0f.x, b0f.y), b1 = pk2(b1f.x, b1f.y);
#pragma unroll
            for (int i = 0; i < 4; i++) {
                float c = (s==0)?a4[i].x:(s==1)?a4[i].y:(s==2)?a4[i].z:a4[i].w;
                ull a2 = pk2(c, c);
                oacc[i][0] = f2m(a2, b0, oacc[i][0]);
                oacc[i][1] = f2m(a2, b1, oacc[i][1]);
            }
        }
    }
    if (dq == 0) {
#pragma unroll
        for (int i = 0; i < 4; i++) zsm[lg*4+i] = 1.0f / (zacc[i] + EPSZ);
    }
    __syncthreads();
#pragma unroll
    for (int i = 0; i < 4; i++) {
        float z = zsm[lg*4+i];
        float2 v0 = up2(oacc[i][0]), v1 = up2(oacc[i][1]);
        float4 o = make_float4(v0.x*z, v0.y*z, v1.x*z, v1.y*z);
        *(float4*)(outg + gbase + (size_t)(l0 + lg*4+i)*D_ + dq*4) = o;
    }
}

extern "C" void kernel_launch(void* const* d_in, const int* in_sizes, int n_in,
                              void* d_out, int out_size) {
    (void)in_sizes; (void)n_in; (void)out_size;
    const float* q = (const float*)d_in[0];
    const float* k = (const float*)d_in[1];
    const float* v = (const float*)d_in[2];
    const float* P = (const float*)d_in[3];
    float* out = (float*)d_out;

    cudaFuncSetAttribute(k1_kv,  cudaFuncAttributeMaxDynamicSharedMemorySize, SMEM1_BYTES);
    cudaFuncSetAttribute(k2_out, cudaFuncAttributeMaxDynamicSharedMemorySize, SMEM2_BYTES);

    k1_kv<<<BH_*CH, 256, SMEM1_BYTES>>>(k, v, P);
    k_reduce<<<(BH_*PART_SZ)/256, 256>>>();
    k2_out<<<BH_*128, 256, SMEM2_BYTES>>>(q, P, out);
}

// round 4
// speedup vs baseline: 1.8137x; 1.8137x over previous
#include <cuda_runtime.h>

typedef unsigned long long ull;

#define B_ 4
#define H_ 8
#define L_ 8192
#define D_ 64
#define M_ 256
#define BH_ (B_*H_)
#define TL 64
#define CH 32
#define ROWS_PER_CHUNK (L_/CH)               // 256
#define TILES_PER_CHUNK (ROWS_PER_CHUNK/TL)  // 4
#define NORMV 0.35355339059327373f           // 64^(-1/4)
#define EPSK 1e-6f
#define EPSZ 1e-6f
#define NT 256

#define PSTRIDE 258
#define QPSTRIDE 260
#define ASTRIDE 68
#define KVSTRIDE 64

#define PART_SZ (M_*D_ + M_)   // 16640 floats per partial

__device__ __align__(16) float g_part[BH_*CH*PART_SZ];
__device__ __align__(16) float g_kv[BH_*M_*D_];
__device__ __align__(16) float g_ksum[BH_*M_];

// ---- packed fp32x2 helpers ----
__device__ __forceinline__ ull pk2(float lo, float hi) {
    ull r; asm("mov.b64 %0, {%1,%2};" : "=l"(r) : "f"(lo), "f"(hi)); return r;
}
__device__ __forceinline__ ull f2m(ull a, ull b, ull c) {
    ull d; asm("fma.rn.f32x2 %0, %1, %2, %3;" : "=l"(d) : "l"(a), "l"(b), "l"(c)); return d;
}
__device__ __forceinline__ float2 up2(ull v) {
    float lo, hi; asm("mov.b64 {%0,%1}, %2;" : "=f"(lo), "=f"(hi) : "l"(v));
    return make_float2(lo, hi);
}

// Load P [256 m][64 d] global -> Psm[d][m] transposed (256 threads)
__device__ __forceinline__ void load_P(float* Psm, const float* __restrict__ Pg, int t) {
    const float4* g4 = (const float4*)Pg;
#pragma unroll
    for (int it = 0; it < 16; it++) {            // 4096 float4 / 256 threads
        int id = t + it * NT;
        int m = id >> 4, c4 = id & 15;
        float4 v = g4[id];
        Psm[(c4*4+0)*PSTRIDE + m] = v.x;
        Psm[(c4*4+1)*PSTRIDE + m] = v.y;
        Psm[(c4*4+2)*PSTRIDE + m] = v.z;
        Psm[(c4*4+3)*PSTRIDE + m] = v.w;
    }
}

// Load 64x64 fp32 tile (scaled) -> At[64][ASTRIDE] (256 threads)
__device__ __forceinline__ void load_tile64(float* At, const float* __restrict__ g,
                                            float scale, int t) {
    const float4* g4 = (const float4*)g;
#pragma unroll
    for (int it = 0; it < 4; it++) {             // 1024 float4 / 256 threads
        int id = t + it * NT;
        int r = id >> 4, c4 = id & 15;
        float4 v = g4[id];
        v.x *= scale; v.y *= scale; v.z *= scale; v.w *= scale;
        *(float4*)(At + r*ASTRIDE + c4*4) = v;
    }
}

// sqn[r] = 0.5 * sum_d At[r][d]^2
__device__ __forceinline__ void compute_sqn(const float* At, float* sqn, int t) {
    if (t < TL) {
        const float4* row = (const float4*)(At + t * ASTRIDE);
        float s = 0.f;
#pragma unroll
        for (int kk = 0; kk < 16; kk++) {
            float4 a = row[kk];
            s += a.x*a.x + a.y*a.y + a.z*a.z + a.w*a.w;
        }
        sqn[t] = 0.5f * s;
    }
}

// qp[64 l][256 m] = exp(At @ Psm - sqn + EPSK)
// thread: lg=t>>4 owns l-rows lg*4..+3, mg=t&15 owns m in {2mg+32j, j=0..7}
// half-warp LDS: 16 consecutive float2 -> conflict-free; other half broadcasts.
__device__ __forceinline__ void project_tile(const float* __restrict__ Psm,
                                             const float* __restrict__ At,
                                             const float* __restrict__ sqn,
                                             float* __restrict__ qp, int t) {
    const int lg = t >> 4;
    const int mo = (t & 15) * 2;
    ull acc[4][8];
#pragma unroll
    for (int i = 0; i < 4; i++)
#pragma unroll
        for (int j = 0; j < 8; j++) acc[i][j] = 0ULL;

    for (int kk = 0; kk < D_; kk += 4) {
        float4 av[4];
#pragma unroll
        for (int i = 0; i < 4; i++)
            av[i] = *(const float4*)(At + (lg*4+i)*ASTRIDE + kk);   // broadcast
#pragma unroll
        for (int s = 0; s < 4; s++) {
            const float* prow = Psm + (kk+s)*PSTRIDE + mo;
            ull b[8];
#pragma unroll
            for (int j = 0; j < 8; j++) {
                float2 bv = *(const float2*)(prow + 32*j);
                b[j] = pk2(bv.x, bv.y);
            }
#pragma unroll
            for (int i = 0; i < 4; i++) {
                float c = (s==0)?av[i].x:(s==1)?av[i].y:(s==2)?av[i].z:av[i].w;
                ull a2 = pk2(c, c);
#pragma unroll
                for (int j = 0; j < 8; j++)
                    acc[i][j] = f2m(a2, b[j], acc[i][j]);
            }
        }
    }
#pragma unroll
    for (int i = 0; i < 4; i++) {
        float s = sqn[lg*4+i];
        float* orow = qp + (lg*4+i)*QPSTRIDE + mo;
#pragma unroll
        for (int j = 0; j < 8; j++) {
            float2 v = up2(acc[i][j]);
            *(float2*)(orow + 32*j) =
                make_float2(__expf(v.x - s + EPSK), __expf(v.y - s + EPSK));
        }
    }
}

#define SMEM1_FLOATS (64*PSTRIDE + 64*QPSTRIDE + 64*ASTRIDE + 64)
#define SMEM1_BYTES  (SMEM1_FLOATS*4)
#define SMEM2_FLOATS (64*PSTRIDE + 64*QPSTRIDE + 64*ASTRIDE + 64 + M_ + 64)
#define SMEM2_BYTES  (SMEM2_FLOATS*4)

// Kernel 1: per (bh, chunk) partial kv[256][64], k_sum[256]
__global__ void __launch_bounds__(NT, 1)
k1_kv(const float* __restrict__ kg, const float* __restrict__ vg,
      const float* __restrict__ Pg) {
    extern __shared__ float smem[];
    float* Psm = smem;
    float* qp  = Psm + 64*PSTRIDE;
    float* At  = qp  + 64*QPSTRIDE;
    float* sqn = At  + 64*ASTRIDE;

    const int t = threadIdx.x;
    const int bh = blockIdx.x / CH;
    const int chunk = blockIdx.x % CH;

    load_P(Psm, Pg, t);

    // kv map: thread owns m-rows mg4*4..+3, d-cols {2dg+8j, j=0..7}
    const int mg4 = t >> 2;
    const int dg  = t & 3;

    ull kvacc[4][8];
#pragma unroll
    for (int i = 0; i < 4; i++)
#pragma unroll
        for (int j = 0; j < 8; j++) kvacc[i][j] = 0ULL;
    float ksacc = 0.f;   // thread t: column sum of qp col t

    const size_t gbase = (size_t)bh * L_ * D_;

    for (int tile = 0; tile < TILES_PER_CHUNK; tile++) {
        const int l0 = chunk * ROWS_PER_CHUNK + tile * TL;
        __syncthreads();
        load_tile64(At, kg + gbase + (size_t)l0*D_, NORMV, t);
        __syncthreads();
        compute_sqn(At, sqn, t);
        __syncthreads();
        project_tile(Psm, At, sqn, qp, t);          // qp = k'
        __syncthreads();
        load_tile64(At, vg + gbase + (size_t)l0*D_, 1.0f, t);
        __syncthreads();
        // kv += k'^T @ v
#pragma unroll 2
        for (int kk = 0; kk < TL; kk++) {
            float4 a4 = *(const float4*)(qp + kk*QPSTRIDE + mg4*4);
            const float* vrow = At + kk*ASTRIDE + dg*2;
            ull b[8];
#pragma unroll
            for (int j = 0; j < 8; j++) {
                float2 bv = *(const float2*)(vrow + 8*j);
                b[j] = pk2(bv.x, bv.y);
            }
            float am[4] = {a4.x, a4.y, a4.z, a4.w};
#pragma unroll
            for (int i = 0; i < 4; i++) {
                ull a2 = pk2(am[i], am[i]);
#pragma unroll
                for (int j = 0; j < 8; j++)
                    kvacc[i][j] = f2m(a2, b[j], kvacc[i][j]);
            }
        }
        // k_sum: column sums of qp (thread t owns column t; conflict-free)
        {
            float s = 0.f;
#pragma unroll
            for (int l = 0; l < TL; l++) s += qp[l*QPSTRIDE + t];
            ksacc += s;
        }
    }
    float* pb = g_part + (size_t)(bh*CH + chunk) * PART_SZ;
#pragma unroll
    for (int i = 0; i < 4; i++)
#pragma unroll
        for (int j = 0; j < 8; j++) {
            float2 v = up2(kvacc[i][j]);
            *(float2*)(pb + (mg4*4+i)*D_ + dg*2 + 8*j) = v;
        }
    pb[M_*D_ + t] = ksacc;
}

// Kernel R: reduce CH partials -> g_kv, g_ksum
__global__ void k_reduce() {
    int idx = blockIdx.x * 256 + threadIdx.x;
    int bh = idx / PART_SZ;
    int r  = idx - bh * PART_SZ;
    const float* p = g_part + (size_t)bh * CH * PART_SZ + r;
    float s = 0.f;
#pragma unroll
    for (int c = 0; c < CH; c++) s += p[(size_t)c * PART_SZ];
    if (r < M_*D_) g_kv[bh*M_*D_ + r] = s;
    else           g_ksum[bh*M_ + (r - M_*D_)] = s;
}

// Kernel 2: q' projection + out = (q' @ kv) * z
__global__ void __launch_bounds__(NT, 1)
k2_out(const float* __restrict__ qg, const float* __restrict__ Pg,
       float* __restrict__ outg) {
    extern __shared__ float smem[];
    float* buf0 = smem;                    // P during projection, then kv
    float* qp   = buf0 + 64*PSTRIDE;
    float* At   = qp   + 64*QPSTRIDE;
    float* sqn  = At   + 64*ASTRIDE;
    float* ksum = sqn  + 64;
    float* zsm  = ksum + M_;

    const int t = threadIdx.x;
    const int bh = blockIdx.x >> 7;
    const int tile = blockIdx.x & 127;
    const int l0 = tile * TL;
    const size_t gbase = (size_t)bh * L_ * D_;

    load_P(buf0, Pg, t);
    load_tile64(At, qg + gbase + (size_t)l0*D_, NORMV, t);
    __syncthreads();
    compute_sqn(At, sqn, t);
    __syncthreads();
    project_tile(buf0, At, sqn, qp, t);    // qp = q'
    __syncthreads();
    // overwrite P buffer with kv [256][64]; load ksum
    {
        const float4* kv4 = (const float4*)(g_kv + (size_t)bh * M_ * D_);
        float4* b4 = (float4*)buf0;
#pragma unroll
        for (int it = 0; it < 16; it++) b4[t + it*NT] = kv4[t + it*NT];
        ksum[t] = g_ksum[bh*M_ + t];
    }
    __syncthreads();

    // output map: lg=t>>4 owns l-rows lg*4..+3, dq=t&15 owns d {2dq+32j, j=0..1}
    const int lg = t >> 4;
    const int dq = t & 15;
    ull oacc[4][2];
    float zacc[4] = {0.f, 0.f, 0.f, 0.f};
#pragma unroll
    for (int i = 0; i < 4; i++) { oacc[i][0] = 0ULL; oacc[i][1] = 0ULL; }
    const bool zlane = (dq == 0);

    for (int kk = 0; kk < M_; kk += 4) {
        float4 a4[4];
#pragma unroll
        for (int i = 0; i < 4; i++)
            a4[i] = *(const float4*)(qp + (lg*4+i)*QPSTRIDE + kk);   // broadcast
        float4 ks4 = *(const float4*)(ksum + kk);
        if (zlane) {
#pragma unroll
            for (int i = 0; i < 4; i++)
                zacc[i] += a4[i].x*ks4.x + a4[i].y*ks4.y + a4[i].z*ks4.z + a4[i].w*ks4.w;
        }
#pragma unroll
        for (int s = 0; s < 4; s++) {
            const float* kvr = buf0 + (kk+s)*KVSTRIDE + dq*2;
            float2 b0f = *(const float2*)(kvr);
            float2 b1f = *(const float2*)(kvr + 32);
            ull b0 = pk2(b0f.x, b0f.y), b1 = pk2(b1f.x, b1f.y);
#pragma unroll
            for (int i = 0; i < 4; i++) {
                float c = (s==0)?a4[i].x:(s==1)?a4[i].y:(s==2)?a4[i].z:a4[i].w;
                ull a2 = pk2(c, c);
                oacc[i][0] = f2m(a2, b0, oacc[i][0]);
                oacc[i][1] = f2m(a2, b1, oacc[i][1]);
            }
        }
    }
    if (zlane) {
#pragma unroll
        for (int i = 0; i < 4; i++) zsm[lg*4+i] = 1.0f / (zacc[i] + EPSZ);
    }
    __syncthreads();
#pragma unroll
    for (int i = 0; i < 4; i++) {
        float z = zsm[lg*4+i];
        float2 v0 = up2(oacc[i][0]), v1 = up2(oacc[i][1]);
        float* orow = outg + gbase + (size_t)(l0 + lg*4+i)*D_ + dq*2;
        *(float2*)(orow)      = make_float2(v0.x*z, v0.y*z);
        *(float2*)(orow + 32) = make_float2(v1.x*z, v1.y*z);
    }
}

extern "C" void kernel_launch(void* const* d_in, const int* in_sizes, int n_in,
                              void* d_out, int out_size) {
    (void)in_sizes; (void)n_in; (void)out_size;
    const float* q = (const float*)d_in[0];
    const float* k = (const float*)d_in[1];
    const float* v = (const float*)d_in[2];
    const float* P = (const float*)d_in[3];
    float* out = (float*)d_out;

    cudaFuncSetAttribute(k1_kv,  cudaFuncAttributeMaxDynamicSharedMemorySize, SMEM1_BYTES);
    cudaFuncSetAttribute(k2_out, cudaFuncAttributeMaxDynamicSharedMemorySize, SMEM2_BYTES);

    k1_kv<<<BH_*CH, NT, SMEM1_BYTES>>>(k, v, P);
    k_reduce<<<(BH_*PART_SZ)/256, 256>>>();
    k2_out<<<BH_*128, NT, SMEM2_BYTES>>>(q, P, out);
}

// round 5
// speedup vs baseline: 2.0944x; 1.1548x over previous
#include <cuda_runtime.h>

typedef unsigned long long ull;

#define B_ 4
#define H_ 8
#define L_ 8192
#define D_ 64
#define M_ 256
#define BH_ (B_*H_)
#define TL 64
#define CH 32
#define ROWS_PER_CHUNK (L_/CH)               // 256
#define TILES_PER_CHUNK (ROWS_PER_CHUNK/TL)  // 4
#define NORMV 0.35355339059327373f           // 64^(-1/4)
#define EPSK 1e-6f
#define EPSZ 1e-6f
#define NT 256

#define PSTRIDE 258
#define QPSTRIDE 260
#define ASTRIDE 68
#define KVSTRIDE 64

#define PART_SZ (M_*D_ + M_)   // 16640 floats per partial

__device__ __align__(16) float g_part[BH_*CH*PART_SZ];
__device__ __align__(16) float g_kv[BH_*M_*D_];
__device__ __align__(16) float g_ksum[BH_*M_];

// ---- packed fp32x2 helpers ----
__device__ __forceinline__ ull pk2(float lo, float hi) {
    ull r; asm("mov.b64 %0, {%1,%2};" : "=l"(r) : "f"(lo), "f"(hi)); return r;
}
__device__ __forceinline__ ull f2m(ull a, ull b, ull c) {
    ull d; asm("fma.rn.f32x2 %0, %1, %2, %3;" : "=l"(d) : "l"(a), "l"(b), "l"(c)); return d;
}
__device__ __forceinline__ float2 up2(ull v) {
    float lo, hi; asm("mov.b64 {%0,%1}, %2;" : "=f"(lo), "=f"(hi) : "l"(v));
    return make_float2(lo, hi);
}

// Load P [256 m][64 d] global -> Psm[d][m] transposed (256 threads)
__device__ __forceinline__ void load_P(float* Psm, const float* __restrict__ Pg, int t) {
    const float4* g4 = (const float4*)Pg;
#pragma unroll
    for (int it = 0; it < 16; it++) {            // 4096 float4 / 256 threads
        int id = t + it * NT;
        int m = id >> 4, c4 = id & 15;
        float4 v = g4[id];
        Psm[(c4*4+0)*PSTRIDE + m] = v.x;
        Psm[(c4*4+1)*PSTRIDE + m] = v.y;
        Psm[(c4*4+2)*PSTRIDE + m] = v.z;
        Psm[(c4*4+3)*PSTRIDE + m] = v.w;
    }
}

// Load 64x64 fp32 tile (scaled) -> At[64][ASTRIDE] (256 threads)
__device__ __forceinline__ void load_tile64(float* At, const float* __restrict__ g,
                                            float scale, int t) {
    const float4* g4 = (const float4*)g;
#pragma unroll
    for (int it = 0; it < 4; it++) {             // 1024 float4 / 256 threads
        int id = t + it * NT;
        int r = id >> 4, c4 = id & 15;
        float4 v = g4[id];
        v.x *= scale; v.y *= scale; v.z *= scale; v.w *= scale;
        *(float4*)(At + r*ASTRIDE + c4*4) = v;
    }
}

// sqn[r] = 0.5 * sum_d At[r][d]^2
__device__ __forceinline__ void compute_sqn(const float* At, float* sqn, int t) {
    if (t < TL) {
        const float4* row = (const float4*)(At + t * ASTRIDE);
        float s = 0.f;
#pragma unroll
        for (int kk = 0; kk < 16; kk++) {
            float4 a = row[kk];
            s += a.x*a.x + a.y*a.y + a.z*a.z + a.w*a.w;
        }
        sqn[t] = 0.5f * s;
    }
}

// qp[64 l][256 m] = exp(At @ Psm - sqn + EPSK)
// thread: lg=t>>4 owns l-rows lg*4..+3, mg=t&15 owns m in {2mg+32j, j=0..7}
__device__ __forceinline__ void project_tile(const float* __restrict__ Psm,
                                             const float* __restrict__ At,
                                             const float* __restrict__ sqn,
                                             float* __restrict__ qp, int t) {
    const int lg = t >> 4;
    const int mo = (t & 15) * 2;
    ull acc[4][8];
#pragma unroll
    for (int i = 0; i < 4; i++)
#pragma unroll
        for (int j = 0; j < 8; j++) acc[i][j] = 0ULL;

    for (int kk = 0; kk < D_; kk += 4) {
        float4 av[4];
#pragma unroll
        for (int i = 0; i < 4; i++)
            av[i] = *(const float4*)(At + (lg*4+i)*ASTRIDE + kk);   // broadcast
#pragma unroll
        for (int s = 0; s < 4; s++) {
            const float* prow = Psm + (kk+s)*PSTRIDE + mo;
            ull b[8];
#pragma unroll
            for (int j = 0; j < 8; j++) {
                float2 bv = *(const float2*)(prow + 32*j);
                b[j] = pk2(bv.x, bv.y);
            }
#pragma unroll
            for (int i = 0; i < 4; i++) {
                float c = (s==0)?av[i].x:(s==1)?av[i].y:(s==2)?av[i].z:av[i].w;
                ull a2 = pk2(c, c);
#pragma unroll
                for (int j = 0; j < 8; j++)
                    acc[i][j] = f2m(a2, b[j], acc[i][j]);
            }
        }
    }
#pragma unroll
    for (int i = 0; i < 4; i++) {
        float s = sqn[lg*4+i];
        float* orow = qp + (lg*4+i)*QPSTRIDE + mo;
#pragma unroll
        for (int j = 0; j < 8; j++) {
            float2 v = up2(acc[i][j]);
            *(float2*)(orow + 32*j) =
                make_float2(__expf(v.x - s + EPSK), __expf(v.y - s + EPSK));
        }
    }
}

#define SMEM1_FLOATS (64*PSTRIDE + 64*QPSTRIDE + 64*ASTRIDE + 64)
#define SMEM1_BYTES  (SMEM1_FLOATS*4)
#define SMEM2_FLOATS (64*PSTRIDE + 128*QPSTRIDE + 64*ASTRIDE + 64 + M_ + 128)
#define SMEM2_BYTES  (SMEM2_FLOATS*4)

// Kernel 1: per (bh, chunk) partial kv[256][64], k_sum[256]
__global__ void __launch_bounds__(NT, 1)
k1_kv(const float* __restrict__ kg, const float* __restrict__ vg,
      const float* __restrict__ Pg) {
    extern __shared__ float smem[];
    float* Psm = smem;
    float* qp  = Psm + 64*PSTRIDE;
    float* At  = qp  + 64*QPSTRIDE;
    float* sqn = At  + 64*ASTRIDE;

    const int t = threadIdx.x;
    const int bh = blockIdx.x / CH;
    const int chunk = blockIdx.x % CH;

    load_P(Psm, Pg, t);

    // kv map: thread owns m-rows mg8*8..+7, d-cols {2dg+16j, j=0..3}
    const int mg8 = t >> 3;
    const int dg  = t & 7;

    ull kvacc[8][4];
#pragma unroll
    for (int i = 0; i < 8; i++)
#pragma unroll
        for (int j = 0; j < 4; j++) kvacc[i][j] = 0ULL;
    float ksacc = 0.f;   // thread t: column sum of qp col t

    const size_t gbase = (size_t)bh * L_ * D_;

    for (int tile = 0; tile < TILES_PER_CHUNK; tile++) {
        const int l0 = chunk * ROWS_PER_CHUNK + tile * TL;
        __syncthreads();
        load_tile64(At, kg + gbase + (size_t)l0*D_, NORMV, t);
        __syncthreads();
        compute_sqn(At, sqn, t);
        __syncthreads();
        project_tile(Psm, At, sqn, qp, t);          // qp = k'
        __syncthreads();
        load_tile64(At, vg + gbase + (size_t)l0*D_, 1.0f, t);
        __syncthreads();
        // kv += k'^T @ v   (8m x 8d per thread)
#pragma unroll 2
        for (int kk = 0; kk < TL; kk++) {
            const float* qrow = qp + kk*QPSTRIDE + mg8*8;
            float4 a0 = *(const float4*)(qrow);
            float4 a1 = *(const float4*)(qrow + 4);
            const float* vrow = At + kk*ASTRIDE + dg*2;
            ull b[4];
#pragma unroll
            for (int j = 0; j < 4; j++) {
                float2 bv = *(const float2*)(vrow + 16*j);
                b[j] = pk2(bv.x, bv.y);
            }
            float am[8] = {a0.x,a0.y,a0.z,a0.w,a1.x,a1.y,a1.z,a1.w};
#pragma unroll
            for (int i = 0; i < 8; i++) {
                ull a2 = pk2(am[i], am[i]);
#pragma unroll
                for (int j = 0; j < 4; j++)
                    kvacc[i][j] = f2m(a2, b[j], kvacc[i][j]);
            }
        }
        // k_sum: column sums of qp (thread t owns column t; conflict-free)
        {
            float s = 0.f;
#pragma unroll
            for (int l = 0; l < TL; l++) s += qp[l*QPSTRIDE + t];
            ksacc += s;
        }
    }
    float* pb = g_part + (size_t)(bh*CH + chunk) * PART_SZ;
#pragma unroll
    for (int i = 0; i < 8; i++)
#pragma unroll
        for (int j = 0; j < 4; j++) {
            float2 v = up2(kvacc[i][j]);
            *(float2*)(pb + (mg8*8+i)*D_ + dg*2 + 16*j) = v;
        }
    pb[M_*D_ + t] = ksacc;
}

// Kernel R: reduce CH partials -> g_kv, g_ksum
__global__ void k_reduce() {
    int idx = blockIdx.x * 256 + threadIdx.x;
    int bh = idx / PART_SZ;
    int r  = idx - bh * PART_SZ;
    const float* p = g_part + (size_t)bh * CH * PART_SZ + r;
    float s = 0.f;
#pragma unroll
    for (int c = 0; c < CH; c++) s += p[(size_t)c * PART_SZ];
    if (r < M_*D_) g_kv[bh*M_*D_ + r] = s;
    else           g_ksum[bh*M_ + (r - M_*D_)] = s;
}

// Kernel 2: 128 l-rows per block: q' projection (two halves) + out = (q'@kv)*z
__global__ void __launch_bounds__(NT, 1)
k2_out(const float* __restrict__ qg, const float* __restrict__ Pg,
       float* __restrict__ outg) {
    extern __shared__ float smem[];
    float* buf0 = smem;                    // P during projection, then kv
    float* qp   = buf0 + 64*PSTRIDE;       // 128 rows
    float* At   = qp   + 128*QPSTRIDE;
    float* sqn  = At   + 64*ASTRIDE;
    float* ksum = sqn  + 64;
    float* zsm  = ksum + M_;               // 128

    const int t = threadIdx.x;
    const int bh = blockIdx.x >> 6;
    const int tile = blockIdx.x & 63;
    const int l0 = tile * 128;
    const size_t gbase = (size_t)bh * L_ * D_;

    load_P(buf0, Pg, t);

#pragma unroll
    for (int half = 0; half < 2; half++) {
        load_tile64(At, qg + gbase + (size_t)(l0 + half*64)*D_, NORMV, t);
        __syncthreads();
        compute_sqn(At, sqn, t);
        __syncthreads();
        project_tile(buf0, At, sqn, qp + half*64*QPSTRIDE, t);   // q'
        __syncthreads();
    }
    // overwrite P buffer with kv [256][64]; load ksum
    {
        const float4* kv4 = (const float4*)(g_kv + (size_t)bh * M_ * D_);
        float4* b4 = (float4*)buf0;
#pragma unroll
        for (int it = 0; it < 16; it++) b4[t + it*NT] = kv4[t + it*NT];
        ksum[t] = g_ksum[bh*M_ + t];
    }
    __syncthreads();

    // output map: lg=t>>4 owns 8 l-rows lg*8..+7, dq=t&15 owns d {2dq+32j, j=0..1}
    const int lg = t >> 4;
    const int dq = t & 15;
    ull oacc[8][2];
    float zacc[8];
#pragma unroll
    for (int i = 0; i < 8; i++) { oacc[i][0] = 0ULL; oacc[i][1] = 0ULL; zacc[i] = 0.f; }
    const bool zlane = (dq == 0);

    for (int kk = 0; kk < M_; kk += 4) {
        float4 a4[8];
#pragma unroll
        for (int i = 0; i < 8; i++)
            a4[i] = *(const float4*)(qp + (lg*8+i)*QPSTRIDE + kk);   // broadcast
        float4 ks4 = *(const float4*)(ksum + kk);
        if (zlane) {
#pragma unroll
            for (int i = 0; i < 8; i++)
                zacc[i] += a4[i].x*ks4.x + a4[i].y*ks4.y + a4[i].z*ks4.z + a4[i].w*ks4.w;
        }
#pragma unroll
        for (int s = 0; s < 4; s++) {
            const float* kvr = buf0 + (kk+s)*KVSTRIDE + dq*2;
            float2 b0f = *(const float2*)(kvr);
            float2 b1f = *(const float2*)(kvr + 32);
            ull b0 = pk2(b0f.x, b0f.y), b1 = pk2(b1f.x, b1f.y);
#pragma unroll
            for (int i = 0; i < 8; i++) {
                float c = (s==0)?a4[i].x:(s==1)?a4[i].y:(s==2)?a4[i].z:a4[i].w;
                ull a2 = pk2(c, c);
                oacc[i][0] = f2m(a2, b0, oacc[i][0]);
                oacc[i][1] = f2m(a2, b1, oacc[i][1]);
            }
        }
    }
    if (zlane) {
#pragma unroll
        for (int i = 0; i < 8; i++) zsm[lg*8+i] = 1.0f / (zacc[i] + EPSZ);
    }
    __syncthreads();
#pragma unroll
    for (int i = 0; i < 8; i++) {
        float z = zsm[lg*8+i];
        float2 v0 = up2(oacc[i][0]), v1 = up2(oacc[i][1]);
        float* orow = outg + gbase + (size_t)(l0 + lg*8+i)*D_ + dq*2;
        *(float2*)(orow)      = make_float2(v0.x*z, v0.y*z);
        *(float2*)(orow + 32) = make_float2(v1.x*z, v1.y*z);
    }
}

extern "C" void kernel_launch(void* const* d_in, const int* in_sizes, int n_in,
                              void* d_out, int out_size) {
    (void)in_sizes; (void)n_in; (void)out_size;
    const float* q = (const float*)d_in[0];
    const float* k = (const float*)d_in[1];
    const float* v = (const float*)d_in[2];
    const float* P = (const float*)d_in[3];
    float* out = (float*)d_out;

    cudaFuncSetAttribute(k1_kv,  cudaFuncAttributeMaxDynamicSharedMemorySize, SMEM1_BYTES);
    cudaFuncSetAttribute(k2_out, cudaFuncAttributeMaxDynamicSharedMemorySize, SMEM2_BYTES);

    k1_kv<<<BH_*CH, NT, SMEM1_BYTES>>>(k, v, P);
    k_reduce<<<(BH_*PART_SZ)/256, 256>>>();
    k2_out<<<BH_*64, NT, SMEM2_BYTES>>>(q, P, out);
}

// round 7
// speedup vs baseline: 2.7752x; 1.3250x over previous
#include <cuda_runtime.h>
#include <cstdint>

typedef unsigned long long ull;
typedef unsigned int u32;

#define B_ 4
#define H_ 8
#define L_ 8192
#define D_ 64
#define M_ 256
#define BH_ (B_*H_)
#define TL 64
#define CH 32
#define ROWS_PER_CHUNK (L_/CH)               // 256
#define TILES_PER_CHUNK (ROWS_PER_CHUNK/TL)  // 4
#define NORMV 0.35355339059327373f           // 64^(-1/4)
#define EPSK 1e-6f
#define EPSZ 1e-6f
#define NT 256

#define PSTRIDE 258
#define QPSTRIDE 260
#define ASTRIDE 68

#define PART_SZ (M_*D_ + M_)   // 16640 floats per partial

__device__ __align__(16) float g_part[BH_*CH*PART_SZ];
__device__ __align__(16) float g_kv[BH_*M_*D_];     // tf32-rounded
__device__ __align__(16) float g_ksum[BH_*M_];      // exact fp32
__device__ __align__(16) float g_Ph[M_*D_];         // tf32 hi
__device__ __align__(16) float g_Pl[M_*D_];         // tf32 lo

// ---- packed fp32x2 helpers (k1) ----
__device__ __forceinline__ ull pk2(float lo, float hi) {
    ull r; asm("mov.b64 %0, {%1,%2};" : "=l"(r) : "f"(lo), "f"(hi)); return r;
}
__device__ __forceinline__ ull f2m(ull a, ull b, ull c) {
    ull d; asm("fma.rn.f32x2 %0, %1, %2, %3;" : "=l"(d) : "l"(a), "l"(b), "l"(c)); return d;
}
__device__ __forceinline__ float2 up2(ull v) {
    float lo, hi; asm("mov.b64 {%0,%1}, %2;" : "=f"(lo), "=f"(hi) : "l"(v));
    return make_float2(lo, hi);
}

// ---- tf32 helpers (k2) ----
__device__ __forceinline__ float tf32r(float x) {
    u32 u; asm("cvt.rna.tf32.f32 %0, %1;" : "=r"(u) : "f"(x));
    return __uint_as_float(u);
}
__device__ __forceinline__ u32 f2u(float x) { return __float_as_uint(x); }
__device__ __forceinline__ void mma8(float* c, const u32* a, u32 b0, u32 b1) {
    asm volatile(
        "mma.sync.aligned.m16n8k8.row.col.f32.tf32.tf32.f32 "
        "{%0,%1,%2,%3}, {%4,%5,%6,%7}, {%8,%9}, {%0,%1,%2,%3};"
        : "+f"(c[0]), "+f"(c[1]), "+f"(c[2]), "+f"(c[3])
        : "r"(a[0]), "r"(a[1]), "r"(a[2]), "r"(a[3]), "r"(b0), "r"(b1));
}

// =============================== k1 (unchanged, proven) ===============================

__device__ __forceinline__ void load_P(float* Psm, const float* __restrict__ Pg, int t) {
    const float4* g4 = (const float4*)Pg;
#pragma unroll
    for (int it = 0; it < 16; it++) {
        int id = t + it * NT;
        int m = id >> 4, c4 = id & 15;
        float4 v = g4[id];
        Psm[(c4*4+0)*PSTRIDE + m] = v.x;
        Psm[(c4*4+1)*PSTRIDE + m] = v.y;
        Psm[(c4*4+2)*PSTRIDE + m] = v.z;
        Psm[(c4*4+3)*PSTRIDE + m] = v.w;
    }
}

__device__ __forceinline__ void load_tile64(float* At, const float* __restrict__ g,
                                            float scale, int t) {
    const float4* g4 = (const float4*)g;
#pragma unroll
    for (int it = 0; it < 4; it++) {
        int id = t + it * NT;
        int r = id >> 4, c4 = id & 15;
        float4 v = g4[id];
        v.x *= scale; v.y *= scale; v.z *= scale; v.w *= scale;
        *(float4*)(At + r*ASTRIDE + c4*4) = v;
    }
}

__device__ __forceinline__ void compute_sqn(const float* At, float* sqn, int t) {
    if (t < TL) {
        const float4* row = (const float4*)(At + t * ASTRIDE);
        float s = 0.f;
#pragma unroll
        for (int kk = 0; kk < 16; kk++) {
            float4 a = row[kk];
            s += a.x*a.x + a.y*a.y + a.z*a.z + a.w*a.w;
        }
        sqn[t] = 0.5f * s;
    }
}

__device__ __forceinline__ void project_tile(const float* __restrict__ Psm,
                                             const float* __restrict__ At,
                                             const float* __restrict__ sqn,
                                             float* __restrict__ qp, int t) {
    const int lg = t >> 4;
    const int mo = (t & 15) * 2;
    ull acc[4][8];
#pragma unroll
    for (int i = 0; i < 4; i++)
#pragma unroll
        for (int j = 0; j < 8; j++) acc[i][j] = 0ULL;

    for (int kk = 0; kk < D_; kk += 4) {
        float4 av[4];
#pragma unroll
        for (int i = 0; i < 4; i++)
            av[i] = *(const float4*)(At + (lg*4+i)*ASTRIDE + kk);
#pragma unroll
        for (int s = 0; s < 4; s++) {
            const float* prow = Psm + (kk+s)*PSTRIDE + mo;
            ull b[8];
#pragma unroll
            for (int j = 0; j < 8; j++) {
                float2 bv = *(const float2*)(prow + 32*j);
                b[j] = pk2(bv.x, bv.y);
            }
#pragma unroll
            for (int i = 0; i < 4; i++) {
                float c = (s==0)?av[i].x:(s==1)?av[i].y:(s==2)?av[i].z:av[i].w;
                ull a2 = pk2(c, c);
#pragma unroll
                for (int j = 0; j < 8; j++)
                    acc[i][j] = f2m(a2, b[j], acc[i][j]);
            }
        }
    }
#pragma unroll
    for (int i = 0; i < 4; i++) {
        float s = sqn[lg*4+i];
        float* orow = qp + (lg*4+i)*QPSTRIDE + mo;
#pragma unroll
        for (int j = 0; j < 8; j++) {
            float2 v = up2(acc[i][j]);
            *(float2*)(orow + 32*j) =
                make_float2(__expf(v.x - s + EPSK), __expf(v.y - s + EPSK));
        }
    }
}

#define SMEM1_FLOATS (64*PSTRIDE + 64*QPSTRIDE + 64*ASTRIDE + 64)
#define SMEM1_BYTES  (SMEM1_FLOATS*4)

__global__ void __launch_bounds__(NT, 1)
k1_kv(const float* __restrict__ kg, const float* __restrict__ vg,
      const float* __restrict__ Pg) {
    extern __shared__ float smem[];
    float* Psm = smem;
    float* qp  = Psm + 64*PSTRIDE;
    float* At  = qp  + 64*QPSTRIDE;
    float* sqn = At  + 64*ASTRIDE;

    const int t = threadIdx.x;
    const int bh = blockIdx.x / CH;
    const int chunk = blockIdx.x % CH;

    load_P(Psm, Pg, t);

    const int mg8 = t >> 3;
    const int dg  = t & 7;

    ull kvacc[8][4];
#pragma unroll
    for (int i = 0; i < 8; i++)
#pragma unroll
        for (int j = 0; j < 4; j++) kvacc[i][j] = 0ULL;
    float ksacc = 0.f;

    const size_t gbase = (size_t)bh * L_ * D_;

    for (int tile = 0; tile < TILES_PER_CHUNK; tile++) {
        const int l0 = chunk * ROWS_PER_CHUNK + tile * TL;
        __syncthreads();
        load_tile64(At, kg + gbase + (size_t)l0*D_, NORMV, t);
        __syncthreads();
        compute_sqn(At, sqn, t);
        __syncthreads();
        project_tile(Psm, At, sqn, qp, t);
        __syncthreads();
        load_tile64(At, vg + gbase + (size_t)l0*D_, 1.0f, t);
        __syncthreads();
#pragma unroll 2
        for (int kk = 0; kk < TL; kk++) {
            const float* qrow = qp + kk*QPSTRIDE + mg8*8;
            float4 a0 = *(const float4*)(qrow);
            float4 a1 = *(const float4*)(qrow + 4);
            const float* vrow = At + kk*ASTRIDE + dg*2;
            ull b[4];
#pragma unroll
            for (int j = 0; j < 4; j++) {
                float2 bv = *(const float2*)(vrow + 16*j);
                b[j] = pk2(bv.x, bv.y);
            }
            float am[8] = {a0.x,a0.y,a0.z,a0.w,a1.x,a1.y,a1.z,a1.w};
#pragma unroll
            for (int i = 0; i < 8; i++) {
                ull a2 = pk2(am[i], am[i]);
#pragma unroll
                for (int j = 0; j < 4; j++)
                    kvacc[i][j] = f2m(a2, b[j], kvacc[i][j]);
            }
        }
        {
            float s = 0.f;
#pragma unroll
            for (int l = 0; l < TL; l++) s += qp[l*QPSTRIDE + t];
            ksacc += s;
        }
    }
    float* pb = g_part + (size_t)(bh*CH + chunk) * PART_SZ;
#pragma unroll
    for (int i = 0; i < 8; i++)
#pragma unroll
        for (int j = 0; j < 4; j++) {
            float2 v = up2(kvacc[i][j]);
            *(float2*)(pb + (mg8*8+i)*D_ + dg*2 + 16*j) = v;
        }
    pb[M_*D_ + t] = ksacc;
}

// ================== prep: P -> tf32 hi/lo split (plain [m][d]) ==================

__global__ void k_prep_P(const float* __restrict__ Pg) {
    int idx = blockIdx.x * 256 + threadIdx.x;   // 16384
    float x = Pg[idx];
    float hi = tf32r(x);
    float lo = tf32r(x - hi);
    g_Ph[idx] = hi;
    g_Pl[idx] = lo;
}

// ========== reduce: partials -> ksum fp32, kv tf32-rounded fp32 ==========

__global__ void k_reduce() {
    int idx = blockIdx.x * 256 + threadIdx.x;
    int bh = idx / PART_SZ;
    int r  = idx - bh * PART_SZ;
    const float* p = g_part + (size_t)bh * CH * PART_SZ + r;
    float s = 0.f;
#pragma unroll
    for (int c = 0; c < CH; c++) s += p[(size_t)c * PART_SZ];
    if (r < M_*D_) g_kv[bh*M_*D_ + r] = tf32r(s);
    else           g_ksum[bh*M_ + (r - M_*D_)] = s;
}

// ============================ k2: mma.sync tf32 pipeline ============================
// smem float offsets:
//  phase A: QH@0 (128*68), QL@8704, PH@17408 (256*68), PL@34816 (ends 52224)
//  phase B: QP@0 (128*260=33280), KV@34816 (256*72=18432, ends 53248)
//  SQN@53248(128) KSUM@53376(256) ZP0@53632(128) ZP1@53760(128) TMP@53888(256)
#define QH_F   0
#define QL_F   8704
#define PH_F   17408
#define PL_F   34816
#define QP_F   0
#define KV_F   34816
#define SQN_F  53248
#define KSUM_F 53376
#define ZP0_F  53632
#define ZP1_F  53760
#define TMP_F  53888
#define K2_FLOATS 54144
#define K2_SMEM (K2_FLOATS*4)
#define QSTR 68
#define QPSTR 260
#define KVSTR 72

__global__ void __launch_bounds__(256, 1)
k2_out(const float* __restrict__ qg, float* __restrict__ outg) {
    extern __shared__ float smf[];
    const int t = threadIdx.x;
    const int lane = t & 31, w = t >> 5;
    const int g = lane >> 2, tig = lane & 3;
    const int bh = blockIdx.x >> 6, tile = blockIdx.x & 63;
    const int l0 = tile * 128;
    const size_t gbase = (size_t)bh * L_ * D_;

    // ---- load P hi/lo into padded smem ----
    {
        const float4* sh = (const float4*)g_Ph;
        const float4* sl = (const float4*)g_Pl;
#pragma unroll
        for (int i = 0; i < 16; i++) {
            int id = t + i * 256;              // 4096 float4
            int r = id >> 4, c4 = id & 15;
            *(float4*)(smf + PH_F + r*QSTR + c4*4) = sh[id];
            *(float4*)(smf + PL_F + r*QSTR + c4*4) = sl[id];
        }
    }
    // ---- load q tile, scale, split, sqn partials ----
    {
        const int r = t >> 1, c0 = (t & 1) * 32;
        const float4* src = (const float4*)(qg + gbase + (size_t)(l0 + r)*D_ + c0);
        float ss = 0.f;
#pragma unroll
        for (int i = 0; i < 8; i++) {
            float4 x = src[i];
            x.x *= NORMV; x.y *= NORMV; x.z *= NORMV; x.w *= NORMV;
            ss += x.x*x.x + x.y*x.y + x.z*x.z + x.w*x.w;
            float4 hv, lv;
            hv.x = tf32r(x.x); lv.x = tf32r(x.x - hv.x);
            hv.y = tf32r(x.y); lv.y = tf32r(x.y - hv.y);
            hv.z = tf32r(x.z); lv.z = tf32r(x.z - hv.z);
            hv.w = tf32r(x.w); lv.w = tf32r(x.w - hv.w);
            *(float4*)(smf + QH_F + r*QSTR + c0 + i*4) = hv;
            *(float4*)(smf + QL_F + r*QSTR + c0 + i*4) = lv;
        }
        smf[TMP_F + t] = ss;
    }
    smf[KSUM_F + t] = g_ksum[bh*M_ + t];
    __syncthreads();
    if (t < 128) smf[SQN_F + t] = 0.5f * (smf[TMP_F + 2*t] + smf[TMP_F + 2*t + 1]);
    __syncthreads();

    // ---- GEMM1: proj[128,256] = (qh+ql) @ (Ph+Pl)^T, 3 products ----
    const int lbase = (w & 3) * 32;
    const int n0base = (w >> 2) * 128;
    float acc[2][16][4];
#pragma unroll
    for (int lt = 0; lt < 2; lt++)
#pragma unroll
        for (int nt = 0; nt < 16; nt++)
#pragma unroll
            for (int i = 0; i < 4; i++) acc[lt][nt][i] = 0.f;

    for (int k8 = 0; k8 < 8; k8++) {
        const int k0 = k8 * 8;
        u32 ah[2][4], al[2][4];
#pragma unroll
        for (int lt = 0; lt < 2; lt++) {
            const int r0 = lbase + lt*16 + g;
            ah[lt][0] = f2u(smf[QH_F + r0*QSTR + k0 + tig]);
            ah[lt][1] = f2u(smf[QH_F + (r0+8)*QSTR + k0 + tig]);
            ah[lt][2] = f2u(smf[QH_F + r0*QSTR + k0 + tig + 4]);
            ah[lt][3] = f2u(smf[QH_F + (r0+8)*QSTR + k0 + tig + 4]);
            al[lt][0] = f2u(smf[QL_F + r0*QSTR + k0 + tig]);
            al[lt][1] = f2u(smf[QL_F + (r0+8)*QSTR + k0 + tig]);
            al[lt][2] = f2u(smf[QL_F + r0*QSTR + k0 + tig + 4]);
            al[lt][3] = f2u(smf[QL_F + (r0+8)*QSTR + k0 + tig + 4]);
        }
#pragma unroll
        for (int nt = 0; nt < 16; nt++) {
            const int n0 = n0base + nt*8;
            u32 bh0 = f2u(smf[PH_F + (n0+g)*QSTR + k0 + tig]);
            u32 bh1 = f2u(smf[PH_F + (n0+g)*QSTR + k0 + tig + 4]);
            u32 bl0 = f2u(smf[PL_F + (n0+g)*QSTR + k0 + tig]);
            u32 bl1 = f2u(smf[PL_F + (n0+g)*QSTR + k0 + tig + 4]);
#pragma unroll
            for (int lt = 0; lt < 2; lt++) {
                mma8(acc[lt][nt], ah[lt], bh0, bh1);
                mma8(acc[lt][nt], ah[lt], bl0, bl1);
                mma8(acc[lt][nt], al[lt], bh0, bh1);
            }
        }
    }
    __syncthreads();   // everyone done reading QH/QL/PH/PL

    // ---- Epilogue 1: exp, z-dot, tf32 round, store q' ----
#pragma unroll
    for (int lt = 0; lt < 2; lt++) {
        const int r1 = lbase + lt*16 + g;
        const int r2 = r1 + 8;
        const float sq1 = smf[SQN_F + r1], sq2 = smf[SQN_F + r2];
        float za1 = 0.f, za2 = 0.f;
#pragma unroll
        for (int nt = 0; nt < 16; nt++) {
            const int n = n0base + nt*8 + 2*tig;
            const float ks0 = smf[KSUM_F + n], ks1 = smf[KSUM_F + n + 1];
            float e00 = __expf(acc[lt][nt][0] - sq1 + EPSK);
            float e01 = __expf(acc[lt][nt][1] - sq1 + EPSK);
            float e10 = __expf(acc[lt][nt][2] - sq2 + EPSK);
            float e11 = __expf(acc[lt][nt][3] - sq2 + EPSK);
            za1 += e00*ks0 + e01*ks1;
            za2 += e10*ks0 + e11*ks1;
            *(float2*)(smf + QP_F + r1*QPSTR + n) = make_float2(tf32r(e00), tf32r(e01));
            *(float2*)(smf + QP_F + r2*QPSTR + n) = make_float2(tf32r(e10), tf32r(e11));
        }
        za1 += __shfl_xor_sync(0xffffffffu, za1, 1);
        za1 += __shfl_xor_sync(0xffffffffu, za1, 2);
        za2 += __shfl_xor_sync(0xffffffffu, za2, 1);
        za2 += __shfl_xor_sync(0xffffffffu, za2, 2);
        if (tig == 0) {
            float* zp = smf + ((w >> 2) ? ZP1_F : ZP0_F);
            zp[r1] = za1;
            zp[r2] = za2;
        }
    }
    // ---- load kv (tf32-rounded) into stride-72 smem ----
    {
        const float4* src = (const float4*)(g_kv + (size_t)bh * M_ * D_);
#pragma unroll
        for (int i = 0; i < 16; i++) {
            int id = t + i * 256;              // 4096 float4
            int m = id >> 4, c4 = id & 15;
            *(float4*)(smf + KV_F + m*KVSTR + c4*4) = src[id];
        }
    }
    __syncthreads();

    // ---- GEMM2: out[128,64] = q'[128,256] @ kv[256,64] ----
    const int r0 = w*16 + g;
    float acc2[8][4];
#pragma unroll
    for (int nt = 0; nt < 8; nt++)
#pragma unroll
        for (int i = 0; i < 4; i++) acc2[nt][i] = 0.f;

    for (int km = 0; km < 32; km++) {
        const int m0 = km * 8;
        u32 a[4];
        a[0] = f2u(smf[QP_F + r0*QPSTR + m0 + tig]);
        a[1] = f2u(smf[QP_F + (r0+8)*QPSTR + m0 + tig]);
        a[2] = f2u(smf[QP_F + r0*QPSTR + m0 + tig + 4]);
        a[3] = f2u(smf[QP_F + (r0+8)*QPSTR + m0 + tig + 4]);
#pragma unroll
        for (int nt = 0; nt < 8; nt++) {
            u32 b0 = f2u(smf[KV_F + (m0+tig)*KVSTR + nt*8 + g]);
            u32 b1 = f2u(smf[KV_F + (m0+tig+4)*KVSTR + nt*8 + g]);
            mma8(acc2[nt], a, b0, b1);
        }
    }

    // ---- Epilogue 2: scale by z, store ----
    {
        const float z1 = 1.0f / (smf[ZP0_F + r0] + smf[ZP1_F + r0] + EPSZ);
        const float z2 = 1.0f / (smf[ZP0_F + r0 + 8] + smf[ZP1_F + r0 + 8] + EPSZ);
        float* o1 = outg + gbase + (size_t)(l0 + r0)*D_;
        float* o2 = outg + gbase + (size_t)(l0 + r0 + 8)*D_;
#pragma unroll
        for (int nt = 0; nt < 8; nt++) {
            const int d = nt*8 + 2*tig;
            *(float2*)(o1 + d) = make_float2(acc2[nt][0]*z1, acc2[nt][1]*z1);
            *(float2*)(o2 + d) = make_float2(acc2[nt][2]*z2, acc2[nt][3]*z2);
        }
    }
}

extern "C" void kernel_launch(void* const* d_in, const int* in_sizes, int n_in,
                              void* d_out, int out_size) {
    (void)in_sizes; (void)n_in; (void)out_size;
    const float* q = (const float*)d_in[0];
    const float* k = (const float*)d_in[1];
    const float* v = (const float*)d_in[2];
    const float* P = (const float*)d_in[3];
    float* out = (float*)d_out;

    cudaFuncSetAttribute(k1_kv,  cudaFuncAttributeMaxDynamicSharedMemorySize, SMEM1_BYTES);
    cudaFuncSetAttribute(k2_out, cudaFuncAttributeMaxDynamicSharedMemorySize, K2_SMEM);

    k_prep_P<<<64, 256>>>(P);
    k1_kv<<<BH_*CH, NT, SMEM1_BYTES>>>(k, v, P);
    k_reduce<<<(BH_*PART_SZ)/256, 256>>>();
    k2_out<<<BH_*64, 256, K2_SMEM>>>(q, out);
}

// round 8
// speedup vs baseline: 3.2426x; 1.1684x over previous
#include <cuda_runtime.h>
#include <cstdint>

typedef unsigned int u32;

#define B_ 4
#define H_ 8
#define L_ 8192
#define D_ 64
#define M_ 256
#define BH_ (B_*H_)
#define CH2 64                              // 64 chunks of 128 l-rows
#define NORMV 0.35355339059327373f          // 64^(-1/4)
#define EPSK 1e-6f
#define EPSZ 1e-6f

#define PART_SZ (M_*D_ + M_)                // 16640 floats per partial

__device__ __align__(16) float g_part[BH_*CH2*PART_SZ];   // ~136 MB
__device__ __align__(16) float g_kv[BH_*M_*D_];           // tf32-rounded
__device__ __align__(16) float g_ksum[BH_*M_];            // fp32
__device__ __align__(16) float g_Ph[M_*D_];               // tf32 hi
__device__ __align__(16) float g_Pl[M_*D_];               // tf32 lo

// ---- tf32 / mma helpers ----
__device__ __forceinline__ float tf32r(float x) {
    u32 u; asm("cvt.rna.tf32.f32 %0, %1;" : "=r"(u) : "f"(x));
    return __uint_as_float(u);
}
__device__ __forceinline__ u32 f2u(float x) { return __float_as_uint(x); }
__device__ __forceinline__ void mma8(float* c, const u32* a, u32 b0, u32 b1) {
    asm volatile(
        "mma.sync.aligned.m16n8k8.row.col.f32.tf32.tf32.f32 "
        "{%0,%1,%2,%3}, {%4,%5,%6,%7}, {%8,%9}, {%0,%1,%2,%3};"
        : "+f"(c[0]), "+f"(c[1]), "+f"(c[2]), "+f"(c[3])
        : "r"(a[0]), "r"(a[1]), "r"(a[2]), "r"(a[3]), "r"(b0), "r"(b1));
}

// ================== prep: P -> tf32 hi/lo split (plain [m][d]) ==================

__global__ void k_prep_P(const float* __restrict__ Pg) {
    int idx = blockIdx.x * 256 + threadIdx.x;   // 16384
    float x = Pg[idx];
    float hi = tf32r(x);
    float lo = tf32r(x - hi);
    g_Ph[idx] = hi;
    g_Pl[idx] = lo;
}

// ============================ k1: mma.sync tf32 pipeline ============================
// smem float offsets:
//  phase A: KH@0 (128*68=8704), KL@8704, PH@17408 (256*68=17408), PL@34816 (ends 52224)
//  phase B (aliases A): qpT@0 (256*132=33792), V@33792 (128*72=9216, ends 43008)
//  tail: SQN1@52224(128) TMP1@52352(256)  -> 52608 floats = 210,432 B
#define KH_F   0
#define KL_F   8704
#define PH_F   17408
#define PL_F   34816
#define QPT_F  0
#define V_F    33792
#define SQN1_F 52224
#define TMP1_F 52352
#define K1_FLOATS 52608
#define K1_SMEM (K1_FLOATS*4)
#define QSTR 68
#define QPT_STR 132
#define VSTR 72

__global__ void __launch_bounds__(256, 1)
k1_mma(const float* __restrict__ kg, const float* __restrict__ vg) {
    extern __shared__ float smf[];
    const int t = threadIdx.x;
    const int lane = t & 31, w = t >> 5;
    const int g = lane >> 2, tig = lane & 3;
    const int bh = blockIdx.x >> 6, tile = blockIdx.x & 63;
    const int l0 = tile * 128;
    const size_t gbase = (size_t)bh * L_ * D_;

    // ---- load P hi/lo into padded smem ----
    {
        const float4* sh = (const float4*)g_Ph;
        const float4* sl = (const float4*)g_Pl;
#pragma unroll
        for (int i = 0; i < 16; i++) {
            int id = t + i * 256;              // 4096 float4
            int r = id >> 4, c4 = id & 15;
            *(float4*)(smf + PH_F + r*QSTR + c4*4) = sh[id];
            *(float4*)(smf + PL_F + r*QSTR + c4*4) = sl[id];
        }
    }
    // ---- load k tile, scale, split, sqn partials ----
    {
        const int r = t >> 1, c0 = (t & 1) * 32;
        const float4* src = (const float4*)(kg + gbase + (size_t)(l0 + r)*D_ + c0);
        float ss = 0.f;
#pragma unroll
        for (int i = 0; i < 8; i++) {
            float4 x = src[i];
            x.x *= NORMV; x.y *= NORMV; x.z *= NORMV; x.w *= NORMV;
            ss += x.x*x.x + x.y*x.y + x.z*x.z + x.w*x.w;
            float4 hv, lv;
            hv.x = tf32r(x.x); lv.x = tf32r(x.x - hv.x);
            hv.y = tf32r(x.y); lv.y = tf32r(x.y - hv.y);
            hv.z = tf32r(x.z); lv.z = tf32r(x.z - hv.z);
            hv.w = tf32r(x.w); lv.w = tf32r(x.w - hv.w);
            *(float4*)(smf + KH_F + r*QSTR + c0 + i*4) = hv;
            *(float4*)(smf + KL_F + r*QSTR + c0 + i*4) = lv;
        }
        smf[TMP1_F + t] = ss;
    }
    __syncthreads();
    if (t < 128) smf[SQN1_F + t] = 0.5f * (smf[TMP1_F + 2*t] + smf[TMP1_F + 2*t + 1]);
    __syncthreads();

    // ---- GEMM1: proj[128,256] = (kh+kl) @ (Ph+Pl)^T, 3 products ----
    const int lbase = (w & 3) * 32;
    const int n0base = (w >> 2) * 128;
    float acc[2][16][4];
#pragma unroll
    for (int lt = 0; lt < 2; lt++)
#pragma unroll
        for (int nt = 0; nt < 16; nt++)
#pragma unroll
            for (int i = 0; i < 4; i++) acc[lt][nt][i] = 0.f;

    for (int k8 = 0; k8 < 8; k8++) {
        const int k0 = k8 * 8;
        u32 ah[2][4], al[2][4];
#pragma unroll
        for (int lt = 0; lt < 2; lt++) {
            const int r0 = lbase + lt*16 + g;
            ah[lt][0] = f2u(smf[KH_F + r0*QSTR + k0 + tig]);
            ah[lt][1] = f2u(smf[KH_F + (r0+8)*QSTR + k0 + tig]);
            ah[lt][2] = f2u(smf[KH_F + r0*QSTR + k0 + tig + 4]);
            ah[lt][3] = f2u(smf[KH_F + (r0+8)*QSTR + k0 + tig + 4]);
            al[lt][0] = f2u(smf[KL_F + r0*QSTR + k0 + tig]);
            al[lt][1] = f2u(smf[KL_F + (r0+8)*QSTR + k0 + tig]);
            al[lt][2] = f2u(smf[KL_F + r0*QSTR + k0 + tig + 4]);
            al[lt][3] = f2u(smf[KL_F + (r0+8)*QSTR + k0 + tig + 4]);
        }
#pragma unroll
        for (int nt = 0; nt < 16; nt++) {
            const int n0 = n0base + nt*8;
            u32 bh0 = f2u(smf[PH_F + (n0+g)*QSTR + k0 + tig]);
            u32 bh1 = f2u(smf[PH_F + (n0+g)*QSTR + k0 + tig + 4]);
            u32 bl0 = f2u(smf[PL_F + (n0+g)*QSTR + k0 + tig]);
            u32 bl1 = f2u(smf[PL_F + (n0+g)*QSTR + k0 + tig + 4]);
#pragma unroll
            for (int lt = 0; lt < 2; lt++) {
                mma8(acc[lt][nt], ah[lt], bh0, bh1);
                mma8(acc[lt][nt], ah[lt], bl0, bl1);
                mma8(acc[lt][nt], al[lt], bh0, bh1);
            }
        }
    }
    __syncthreads();   // all warps done reading KH/KL/PH/PL

    // ---- Epilogue 1: exp, tf32 round, store TRANSPOSED qpT[m][l] ----
#pragma unroll
    for (int lt = 0; lt < 2; lt++) {
        const int r1 = lbase + lt*16 + g;
        const int r2 = r1 + 8;
        const float sq1 = smf[SQN1_F + r1], sq2 = smf[SQN1_F + r2];
#pragma unroll
        for (int nt = 0; nt < 16; nt++) {
            const int n = n0base + nt*8 + 2*tig;
            float e00 = __expf(acc[lt][nt][0] - sq1 + EPSK);
            float e01 = __expf(acc[lt][nt][1] - sq1 + EPSK);
            float e10 = __expf(acc[lt][nt][2] - sq2 + EPSK);
            float e11 = __expf(acc[lt][nt][3] - sq2 + EPSK);
            smf[QPT_F + n*QPT_STR + r1]     = tf32r(e00);
            smf[QPT_F + (n+1)*QPT_STR + r1] = tf32r(e01);
            smf[QPT_F + n*QPT_STR + r2]     = tf32r(e10);
            smf[QPT_F + (n+1)*QPT_STR + r2] = tf32r(e11);
        }
    }
    // ---- load v tile (tf32-rounded) into stride-72 smem ----
    {
        const float4* src = (const float4*)(vg + gbase + (size_t)l0*D_);
#pragma unroll
        for (int i = 0; i < 8; i++) {
            int id = t + i * 256;              // 2048 float4
            int l = id >> 4, c4 = id & 15;
            float4 x = src[id];
            x.x = tf32r(x.x); x.y = tf32r(x.y); x.z = tf32r(x.z); x.w = tf32r(x.w);
            *(float4*)(smf + V_F + l*VSTR + c4*4) = x;
        }
    }
    __syncthreads();

    // ---- GEMM2: kv_partial[256,64] = qpT[256,128] @ v[128,64] ----
    const int m0 = w * 32;                    // warp owns m rows m0..m0+31
    float acc2[2][8][4];
#pragma unroll
    for (int mt = 0; mt < 2; mt++)
#pragma unroll
        for (int nt = 0; nt < 8; nt++)
#pragma unroll
            for (int i = 0; i < 4; i++) acc2[mt][nt][i] = 0.f;

    for (int k8 = 0; k8 < 16; k8++) {
        const int lk = k8 * 8;
        u32 a[2][4];
#pragma unroll
        for (int mt = 0; mt < 2; mt++) {
            const int r0 = m0 + mt*16 + g;
            a[mt][0] = f2u(smf[QPT_F + r0*QPT_STR + lk + tig]);
            a[mt][1] = f2u(smf[QPT_F + (r0+8)*QPT_STR + lk + tig]);
            a[mt][2] = f2u(smf[QPT_F + r0*QPT_STR + lk + tig + 4]);
            a[mt][3] = f2u(smf[QPT_F + (r0+8)*QPT_STR + lk + tig + 4]);
        }
#pragma unroll
        for (int nt = 0; nt < 8; nt++) {
            u32 b0 = f2u(smf[V_F + (lk+tig)*VSTR + nt*8 + g]);
            u32 b1 = f2u(smf[V_F + (lk+tig+4)*VSTR + nt*8 + g]);
#pragma unroll
            for (int mt = 0; mt < 2; mt++)
                mma8(acc2[mt][nt], a[mt], b0, b1);
        }
    }

    // ---- write kv partial + ksum partial ----
    float* pb = g_part + (size_t)(bh*CH2 + tile) * PART_SZ;
#pragma unroll
    for (int mt = 0; mt < 2; mt++) {
        const int r1 = m0 + mt*16 + g, r2 = r1 + 8;
#pragma unroll
        for (int nt = 0; nt < 8; nt++) {
            const int d = nt*8 + 2*tig;
            *(float2*)(pb + r1*D_ + d) = make_float2(acc2[mt][nt][0], acc2[mt][nt][1]);
            *(float2*)(pb + r2*D_ + d) = make_float2(acc2[mt][nt][2], acc2[mt][nt][3]);
        }
    }
    // ksum: thread t sums qpT row t over l (tf32-rounded k'; positive values,
    // rounding averages out ~1e-5)
    {
        float s = 0.f;
        const float* row = smf + QPT_F + t*QPT_STR;
#pragma unroll 4
        for (int l = 0; l < 128; l++) s += row[l];
        pb[M_*D_ + t] = s;
    }
}

// ========== reduce: partials -> ksum fp32, kv tf32-rounded fp32 ==========

__global__ void k_reduce() {
    int idx = blockIdx.x * 256 + threadIdx.x;
    int bh = idx / PART_SZ;
    int r  = idx - bh * PART_SZ;
    const float* p = g_part + (size_t)bh * CH2 * PART_SZ + r;
    float s = 0.f;
#pragma unroll
    for (int c = 0; c < CH2; c++) s += p[(size_t)c * PART_SZ];
    if (r < M_*D_) g_kv[bh*M_*D_ + r] = tf32r(s);
    else           g_ksum[bh*M_ + (r - M_*D_)] = s;
}

// ============================ k2: mma.sync tf32 pipeline (R7, proven) ============================
#define QH_F   0
#define QL_F   8704
#define PH2_F  17408
#define PL2_F  34816
#define QP_F   0
#define KV_F   34816
#define SQN_F  53248
#define KSUM_F 53376
#define ZP0_F  53632
#define ZP1_F  53760
#define TMP_F  53888
#define K2_FLOATS 54144
#define K2_SMEM (K2_FLOATS*4)
#define QPSTR 260
#define KVSTR 72

__global__ void __launch_bounds__(256, 1)
k2_out(const float* __restrict__ qg, float* __restrict__ outg) {
    extern __shared__ float smf[];
    const int t = threadIdx.x;
    const int lane = t & 31, w = t >> 5;
    const int g = lane >> 2, tig = lane & 3;
    const int bh = blockIdx.x >> 6, tile = blockIdx.x & 63;
    const int l0 = tile * 128;
    const size_t gbase = (size_t)bh * L_ * D_;

    // ---- load P hi/lo into padded smem ----
    {
        const float4* sh = (const float4*)g_Ph;
        const float4* sl = (const float4*)g_Pl;
#pragma unroll
        for (int i = 0; i < 16; i++) {
            int id = t + i * 256;
            int r = id >> 4, c4 = id & 15;
            *(float4*)(smf + PH2_F + r*QSTR + c4*4) = sh[id];
            *(float4*)(smf + PL2_F + r*QSTR + c4*4) = sl[id];
        }
    }
    // ---- load q tile, scale, split, sqn partials ----
    {
        const int r = t >> 1, c0 = (t & 1) * 32;
        const float4* src = (const float4*)(qg + gbase + (size_t)(l0 + r)*D_ + c0);
        float ss = 0.f;
#pragma unroll
        for (int i = 0; i < 8; i++) {
            float4 x = src[i];
            x.x *= NORMV; x.y *= NORMV; x.z *= NORMV; x.w *= NORMV;
            ss += x.x*x.x + x.y*x.y + x.z*x.z + x.w*x.w;
            float4 hv, lv;
            hv.x = tf32r(x.x); lv.x = tf32r(x.x - hv.x);
            hv.y = tf32r(x.y); lv.y = tf32r(x.y - hv.y);
            hv.z = tf32r(x.z); lv.z = tf32r(x.z - hv.z);
            hv.w = tf32r(x.w); lv.w = tf32r(x.w - hv.w);
            *(float4*)(smf + QH_F + r*QSTR + c0 + i*4) = hv;
            *(float4*)(smf + QL_F + r*QSTR + c0 + i*4) = lv;
        }
        smf[TMP_F + t] = ss;
    }
    smf[KSUM_F + t] = g_ksum[bh*M_ + t];
    __syncthreads();
    if (t < 128) smf[SQN_F + t] = 0.5f * (smf[TMP_F + 2*t] + smf[TMP_F + 2*t + 1]);
    __syncthreads();

    // ---- GEMM1: proj[128,256] = (qh+ql) @ (Ph+Pl)^T, 3 products ----
    const int lbase = (w & 3) * 32;
    const int n0base = (w >> 2) * 128;
    float acc[2][16][4];
#pragma unroll
    for (int lt = 0; lt < 2; lt++)
#pragma unroll
        for (int nt = 0; nt < 16; nt++)
#pragma unroll
            for (int i = 0; i < 4; i++) acc[lt][nt][i] = 0.f;

    for (int k8 = 0; k8 < 8; k8++) {
        const int k0 = k8 * 8;
        u32 ah[2][4], al[2][4];
#pragma unroll
        for (int lt = 0; lt < 2; lt++) {
            const int r0 = lbase + lt*16 + g;
            ah[lt][0] = f2u(smf[QH_F + r0*QSTR + k0 + tig]);
            ah[lt][1] = f2u(smf[QH_F + (r0+8)*QSTR + k0 + tig]);
            ah[lt][2] = f2u(smf[QH_F + r0*QSTR + k0 + tig + 4]);
            ah[lt][3] = f2u(smf[QH_F + (r0+8)*QSTR + k0 + tig + 4]);
            al[lt][0] = f2u(smf[QL_F + r0*QSTR + k0 + tig]);
            al[lt][1] = f2u(smf[QL_F + (r0+8)*QSTR + k0 + tig]);
            al[lt][2] = f2u(smf[QL_F + r0*QSTR + k0 + tig + 4]);
            al[lt][3] = f2u(smf[QL_F + (r0+8)*QSTR + k0 + tig + 4]);
        }
#pragma unroll
        for (int nt = 0; nt < 16; nt++) {
            const int n0 = n0base + nt*8;
            u32 bh0 = f2u(smf[PH2_F + (n0+g)*QSTR + k0 + tig]);
            u32 bh1 = f2u(smf[PH2_F + (n0+g)*QSTR + k0 + tig + 4]);
            u32 bl0 = f2u(smf[PL2_F + (n0+g)*QSTR + k0 + tig]);
            u32 bl1 = f2u(smf[PL2_F + (n0+g)*QSTR + k0 + tig + 4]);
#pragma unroll
            for (int lt = 0; lt < 2; lt++) {
                mma8(acc[lt][nt], ah[lt], bh0, bh1);
                mma8(acc[lt][nt], ah[lt], bl0, bl1);
                mma8(acc[lt][nt], al[lt], bh0, bh1);
            }
        }
    }
    __syncthreads();

    // ---- Epilogue 1: exp, z-dot, tf32 round, store q' ----
#pragma unroll
    for (int lt = 0; lt < 2; lt++) {
        const int r1 = lbase + lt*16 + g;
        const int r2 = r1 + 8;
        const float sq1 = smf[SQN_F + r1], sq2 = smf[SQN_F + r2];
        float za1 = 0.f, za2 = 0.f;
#pragma unroll
        for (int nt = 0; nt < 16; nt++) {
            const int n = n0base + nt*8 + 2*tig;
            const float ks0 = smf[KSUM_F + n], ks1 = smf[KSUM_F + n + 1];
            float e00 = __expf(acc[lt][nt][0] - sq1 + EPSK);
            float e01 = __expf(acc[lt][nt][1] - sq1 + EPSK);
            float e10 = __expf(acc[lt][nt][2] - sq2 + EPSK);
            float e11 = __expf(acc[lt][nt][3] - sq2 + EPSK);
            za1 += e00*ks0 + e01*ks1;
            za2 += e10*ks0 + e11*ks1;
            *(float2*)(smf + QP_F + r1*QPSTR + n) = make_float2(tf32r(e00), tf32r(e01));
            *(float2*)(smf + QP_F + r2*QPSTR + n) = make_float2(tf32r(e10), tf32r(e11));
        }
        za1 += __shfl_xor_sync(0xffffffffu, za1, 1);
        za1 += __shfl_xor_sync(0xffffffffu, za1, 2);
        za2 += __shfl_xor_sync(0xffffffffu, za2, 1);
        za2 += __shfl_xor_sync(0xffffffffu, za2, 2);
        if (tig == 0) {
            float* zp = smf + ((w >> 2) ? ZP1_F : ZP0_F);
            zp[r1] = za1;
            zp[r2] = za2;
        }
    }
    // ---- load kv (tf32-rounded) into stride-72 smem ----
    {
        const float4* src = (const float4*)(g_kv + (size_t)bh * M_ * D_);
#pragma unroll
        for (int i = 0; i < 16; i++) {
            int id = t + i * 256;
            int m = id >> 4, c4 = id & 15;
            *(float4*)(smf + KV_F + m*KVSTR + c4*4) = src[id];
        }
    }
    __syncthreads();

    // ---- GEMM2: out[128,64] = q'[128,256] @ kv[256,64] ----
    const int r0 = w*16 + g;
    float acc2[8][4];
#pragma unroll
    for (int nt = 0; nt < 8; nt++)
#pragma unroll
        for (int i = 0; i < 4; i++) acc2[nt][i] = 0.f;

    for (int km = 0; km < 32; km++) {
        const int m0 = km * 8;
        u32 a[4];
        a[0] = f2u(smf[QP_F + r0*QPSTR + m0 + tig]);
        a[1] = f2u(smf[QP_F + (r0+8)*QPSTR + m0 + tig]);
        a[2] = f2u(smf[QP_F + r0*QPSTR + m0 + tig + 4]);
        a[3] = f2u(smf[QP_F + (r0+8)*QPSTR + m0 + tig + 4]);
#pragma unroll
        for (int nt = 0; nt < 8; nt++) {
            u32 b0 = f2u(smf[KV_F + (m0+tig)*KVSTR + nt*8 + g]);
            u32 b1 = f2u(smf[KV_F + (m0+tig+4)*KVSTR + nt*8 + g]);
            mma8(acc2[nt], a, b0, b1);
        }
    }

    // ---- Epilogue 2: scale by z, store ----
    {
        const float z1 = 1.0f / (smf[ZP0_F + r0] + smf[ZP1_F + r0] + EPSZ);
        const float z2 = 1.0f / (smf[ZP0_F + r0 + 8] + smf[ZP1_F + r0 + 8] + EPSZ);
        float* o1 = outg + gbase + (size_t)(l0 + r0)*D_;
        float* o2 = outg + gbase + (size_t)(l0 + r0 + 8)*D_;
#pragma unroll
        for (int nt = 0; nt < 8; nt++) {
            const int d = nt*8 + 2*tig;
            *(float2*)(o1 + d) = make_float2(acc2[nt][0]*z1, acc2[nt][1]*z1);
            *(float2*)(o2 + d) = make_float2(acc2[nt][2]*z2, acc2[nt][3]*z2);
        }
    }
}

extern "C" void kernel_launch(void* const* d_in, const int* in_sizes, int n_in,
                              void* d_out, int out_size) {
    (void)in_sizes; (void)n_in; (void)out_size;
    const float* q = (const float*)d_in[0];
    const float* k = (const float*)d_in[1];
    const float* v = (const float*)d_in[2];
    const float* P = (const float*)d_in[3];
    float* out = (float*)d_out;

    cudaFuncSetAttribute(k1_mma, cudaFuncAttributeMaxDynamicSharedMemorySize, K1_SMEM);
    cudaFuncSetAttribute(k2_out, cudaFuncAttributeMaxDynamicSharedMemorySize, K2_SMEM);

    k_prep_P<<<64, 256>>>(P);
    k1_mma<<<BH_*CH2, 256, K1_SMEM>>>(k, v);
    k_reduce<<<(BH_*PART_SZ)/256, 256>>>();
    k2_out<<<BH_*CH2, 256, K2_SMEM>>>(q, out);
}

// round 9
// speedup vs baseline: 3.2689x; 1.0081x over previous
#include <cuda_runtime.h>
#include <cstdint>

typedef unsigned int u32;

#define B_ 4
#define H_ 8
#define L_ 8192
#define D_ 64
#define M_ 256
#define BH_ (B_*H_)
#define CH2 64                              // 64 chunks of 128 l-rows
#define NORMV 0.35355339059327373f          // 64^(-1/4)
#define EPSK 1e-6f
#define EPSZ 1e-6f

#define PART_SZ (M_*D_ + M_)                // 16640 floats per partial

__device__ __align__(16) float g_part[BH_*CH2*PART_SZ];   // ~136 MB
__device__ __align__(16) float g_kv[BH_*M_*D_];           // tf32-rounded
__device__ __align__(16) float g_ksum[BH_*M_];            // fp32
__device__ __align__(16) float g_Ph[M_*D_];               // tf32 hi
__device__ __align__(16) float g_Pl[M_*D_];               // tf32 lo

// ---- tf32 / mma helpers ----
__device__ __forceinline__ float tf32r(float x) {
    u32 u; asm("cvt.rna.tf32.f32 %0, %1;" : "=r"(u) : "f"(x));
    return __uint_as_float(u);
}
__device__ __forceinline__ u32 f2u(float x) { return __float_as_uint(x); }
__device__ __forceinline__ void mma8(float* c, const u32* a, u32 b0, u32 b1) {
    asm volatile(
        "mma.sync.aligned.m16n8k8.row.col.f32.tf32.tf32.f32 "
        "{%0,%1,%2,%3}, {%4,%5,%6,%7}, {%8,%9}, {%0,%1,%2,%3};"
        : "+f"(c[0]), "+f"(c[1]), "+f"(c[2]), "+f"(c[3])
        : "r"(a[0]), "r"(a[1]), "r"(a[2]), "r"(a[3]), "r"(b0), "r"(b1));
}

// ================== prep: P -> tf32 hi/lo split (plain [m][d]) ==================

__global__ void k_prep_P(const float* __restrict__ Pg) {
    int idx = blockIdx.x * 256 + threadIdx.x;   // 16384
    float x = Pg[idx];
    float hi = tf32r(x);
    float lo = tf32r(x - hi);
    g_Ph[idx] = hi;
    g_Pl[idx] = lo;
}

// ============================ k1: mma.sync tf32 pipeline ============================
// smem float offsets:
//  phase A: KH@0 (128*68=8704), KL@8704, PH@17408 (256*68=17408), PL@34816 (ends 52224)
//  phase B (aliases A): qpT@0 (256*132=33792), V@33792 (128*72=9216, ends 43008)
//  tail: SQN1@52224(128) TMP1@52352(256) PKS@52608(1024)
#define KH_F   0
#define KL_F   8704
#define PH_F   17408
#define PL_F   34816
#define QPT_F  0
#define V_F    33792
#define SQN1_F 52224
#define TMP1_F 52352
#define PKS_F  52608
#define K1_FLOATS 53632
#define K1_SMEM (K1_FLOATS*4)
#define QSTR 68
#define QPT_STR 132
#define VSTR 72

__global__ void __launch_bounds__(256, 1)
k1_mma(const float* __restrict__ kg, const float* __restrict__ vg) {
    extern __shared__ float smf[];
    const int t = threadIdx.x;
    const int lane = t & 31, w = t >> 5;
    const int g = lane >> 2, tig = lane & 3;
    const int bh = blockIdx.x >> 6, tile = blockIdx.x & 63;
    const int l0 = tile * 128;
    const size_t gbase = (size_t)bh * L_ * D_;

    // ---- load P hi/lo into padded smem ----
    {
        const float4* sh = (const float4*)g_Ph;
        const float4* sl = (const float4*)g_Pl;
#pragma unroll
        for (int i = 0; i < 16; i++) {
            int id = t + i * 256;              // 4096 float4
            int r = id >> 4, c4 = id & 15;
            *(float4*)(smf + PH_F + r*QSTR + c4*4) = sh[id];
            *(float4*)(smf + PL_F + r*QSTR + c4*4) = sl[id];
        }
    }
    // ---- load k tile, scale, split, sqn partials ----
    {
        const int r = t >> 1, c0 = (t & 1) * 32;
        const float4* src = (const float4*)(kg + gbase + (size_t)(l0 + r)*D_ + c0);
        float ss = 0.f;
#pragma unroll
        for (int i = 0; i < 8; i++) {
            float4 x = src[i];
            x.x *= NORMV; x.y *= NORMV; x.z *= NORMV; x.w *= NORMV;
            ss += x.x*x.x + x.y*x.y + x.z*x.z + x.w*x.w;
            float4 hv, lv;
            hv.x = tf32r(x.x); lv.x = tf32r(x.x - hv.x);
            hv.y = tf32r(x.y); lv.y = tf32r(x.y - hv.y);
            hv.z = tf32r(x.z); lv.z = tf32r(x.z - hv.z);
            hv.w = tf32r(x.w); lv.w = tf32r(x.w - hv.w);
            *(float4*)(smf + KH_F + r*QSTR + c0 + i*4) = hv;
            *(float4*)(smf + KL_F + r*QSTR + c0 + i*4) = lv;
        }
        smf[TMP1_F + t] = ss;
    }
    __syncthreads();
    if (t < 128) smf[SQN1_F + t] = 0.5f * (smf[TMP1_F + 2*t] + smf[TMP1_F + 2*t + 1]);
    __syncthreads();

    // ---- GEMM1: proj[128,256] = (kh+kl) @ (Ph+Pl)^T, 3 products ----
    const int lbase = (w & 3) * 32;
    const int n0base = (w >> 2) * 128;
    float acc[2][16][4];
#pragma unroll
    for (int lt = 0; lt < 2; lt++)
#pragma unroll
        for (int nt = 0; nt < 16; nt++)
#pragma unroll
            for (int i = 0; i < 4; i++) acc[lt][nt][i] = 0.f;

    for (int k8 = 0; k8 < 8; k8++) {
        const int k0 = k8 * 8;
        u32 ah[2][4], al[2][4];
#pragma unroll
        for (int lt = 0; lt < 2; lt++) {
            const int r0 = lbase + lt*16 + g;
            ah[lt][0] = f2u(smf[KH_F + r0*QSTR + k0 + tig]);
            ah[lt][1] = f2u(smf[KH_F + (r0+8)*QSTR + k0 + tig]);
            ah[lt][2] = f2u(smf[KH_F + r0*QSTR + k0 + tig + 4]);
            ah[lt][3] = f2u(smf[KH_F + (r0+8)*QSTR + k0 + tig + 4]);
            al[lt][0] = f2u(smf[KL_F + r0*QSTR + k0 + tig]);
            al[lt][1] = f2u(smf[KL_F + (r0+8)*QSTR + k0 + tig]);
            al[lt][2] = f2u(smf[KL_F + r0*QSTR + k0 + tig + 4]);
            al[lt][3] = f2u(smf[KL_F + (r0+8)*QSTR + k0 + tig + 4]);
        }
#pragma unroll
        for (int nt = 0; nt < 16; nt++) {
            const int n0 = n0base + nt*8;
            u32 bh0 = f2u(smf[PH_F + (n0+g)*QSTR + k0 + tig]);
            u32 bh1 = f2u(smf[PH_F + (n0+g)*QSTR + k0 + tig + 4]);
            u32 bl0 = f2u(smf[PL_F + (n0+g)*QSTR + k0 + tig]);
            u32 bl1 = f2u(smf[PL_F + (n0+g)*QSTR + k0 + tig + 4]);
#pragma unroll
            for (int lt = 0; lt < 2; lt++) {
                mma8(acc[lt][nt], ah[lt], bh0, bh1);
                mma8(acc[lt][nt], ah[lt], bl0, bl1);
                mma8(acc[lt][nt], al[lt], bh0, bh1);
            }
        }
    }
    __syncthreads();   // all warps done reading KH/KL/PH/PL

    // ---- Epilogue 1: exp, tf32 store TRANSPOSED qpT[m][l], ksum from registers ----
    {
        float sqa[2][2];
#pragma unroll
        for (int lt = 0; lt < 2; lt++) {
            const int r1 = lbase + lt*16 + g;
            sqa[lt][0] = smf[SQN1_F + r1];
            sqa[lt][1] = smf[SQN1_F + r1 + 8];
        }
#pragma unroll
        for (int nt = 0; nt < 16; nt++) {
            const int n = n0base + nt*8 + 2*tig;
            float cs0 = 0.f, cs1 = 0.f;
#pragma unroll
            for (int lt = 0; lt < 2; lt++) {
                const int r1 = lbase + lt*16 + g;
                const int r2 = r1 + 8;
                float e00 = __expf(acc[lt][nt][0] - sqa[lt][0] + EPSK);
                float e01 = __expf(acc[lt][nt][1] - sqa[lt][0] + EPSK);
                float e10 = __expf(acc[lt][nt][2] - sqa[lt][1] + EPSK);
                float e11 = __expf(acc[lt][nt][3] - sqa[lt][1] + EPSK);
                cs0 += e00 + e10;
                cs1 += e01 + e11;
                smf[QPT_F + n*QPT_STR + r1]     = tf32r(e00);
                smf[QPT_F + (n+1)*QPT_STR + r1] = tf32r(e01);
                smf[QPT_F + n*QPT_STR + r2]     = tf32r(e10);
                smf[QPT_F + (n+1)*QPT_STR + r2] = tf32r(e11);
            }
            // reduce across the 8 row-groups (g) of this warp
            cs0 += __shfl_xor_sync(0xffffffffu, cs0, 4);
            cs0 += __shfl_xor_sync(0xffffffffu, cs0, 8);
            cs0 += __shfl_xor_sync(0xffffffffu, cs0, 16);
            cs1 += __shfl_xor_sync(0xffffffffu, cs1, 4);
            cs1 += __shfl_xor_sync(0xffffffffu, cs1, 8);
            cs1 += __shfl_xor_sync(0xffffffffu, cs1, 16);
            if (lane < 4) {
                smf[PKS_F + w*128 + nt*8 + 2*tig]     = cs0;
                smf[PKS_F + w*128 + nt*8 + 2*tig + 1] = cs1;
            }
        }
    }
    // ---- load v tile (tf32-rounded) into stride-72 smem ----
    {
        const float4* src = (const float4*)(vg + gbase + (size_t)l0*D_);
#pragma unroll
        for (int i = 0; i < 8; i++) {
            int id = t + i * 256;              // 2048 float4
            int l = id >> 4, c4 = id & 15;
            float4 x = src[id];
            x.x = tf32r(x.x); x.y = tf32r(x.y); x.z = tf32r(x.z); x.w = tf32r(x.w);
            *(float4*)(smf + V_F + l*VSTR + c4*4) = x;
        }
    }
    __syncthreads();

    // ---- GEMM2: kv_partial[256,64] = qpT[256,128] @ v[128,64] ----
    const int m0 = w * 32;                    // warp owns m rows m0..m0+31
    float acc2[2][8][4];
#pragma unroll
    for (int mt = 0; mt < 2; mt++)
#pragma unroll
        for (int nt = 0; nt < 8; nt++)
#pragma unroll
            for (int i = 0; i < 4; i++) acc2[mt][nt][i] = 0.f;

#pragma unroll 2
    for (int k8 = 0; k8 < 16; k8++) {
        const int lk = k8 * 8;
        u32 a[2][4];
#pragma unroll
        for (int mt = 0; mt < 2; mt++) {
            const int r0 = m0 + mt*16 + g;
            a[mt][0] = f2u(smf[QPT_F + r0*QPT_STR + lk + tig]);
            a[mt][1] = f2u(smf[QPT_F + (r0+8)*QPT_STR + lk + tig]);
            a[mt][2] = f2u(smf[QPT_F + r0*QPT_STR + lk + tig + 4]);
            a[mt][3] = f2u(smf[QPT_F + (r0+8)*QPT_STR + lk + tig + 4]);
        }
#pragma unroll
        for (int nt = 0; nt < 8; nt++) {
            u32 b0 = f2u(smf[V_F + (lk+tig)*VSTR + nt*8 + g]);
            u32 b1 = f2u(smf[V_F + (lk+tig+4)*VSTR + nt*8 + g]);
#pragma unroll
            for (int mt = 0; mt < 2; mt++)
                mma8(acc2[mt][nt], a[mt], b0, b1);
        }
    }

    // ---- write kv partial + ksum partial ----
    float* pb = g_part + (size_t)(bh*CH2 + tile) * PART_SZ;
#pragma unroll
    for (int mt = 0; mt < 2; mt++) {
        const int r1 = m0 + mt*16 + g, r2 = r1 + 8;
#pragma unroll
        for (int nt = 0; nt < 8; nt++) {
            const int d = nt*8 + 2*tig;
            *(float2*)(pb + r1*D_ + d) = make_float2(acc2[mt][nt][0], acc2[mt][nt][1]);
            *(float2*)(pb + r2*D_ + d) = make_float2(acc2[mt][nt][2], acc2[mt][nt][3]);
        }
    }
    // ksum: 4-warp partial sum per column (registers->pks->final, no conflicts)
    {
        const int nloc = t & 127;
        const int wb = (t >> 7) * 4;
        float s = smf[PKS_F + (wb+0)*128 + nloc]
                + smf[PKS_F + (wb+1)*128 + nloc]
                + smf[PKS_F + (wb+2)*128 + nloc]
                + smf[PKS_F + (wb+3)*128 + nloc];
        pb[M_*D_ + t] = s;
    }
}

// ========== reduce: partials -> ksum fp32, kv tf32-rounded fp32 ==========

__global__ void k_reduce() {
    int idx = blockIdx.x * 256 + threadIdx.x;
    int bh = idx / PART_SZ;
    int r  = idx - bh * PART_SZ;
    const float* p = g_part + (size_t)bh * CH2 * PART_SZ + r;
    float s = 0.f;
#pragma unroll
    for (int c = 0; c < CH2; c++) s += p[(size_t)c * PART_SZ];
    if (r < M_*D_) g_kv[bh*M_*D_ + r] = tf32r(s);
    else           g_ksum[bh*M_ + (r - M_*D_)] = s;
}

// ============================ k2: mma.sync tf32 pipeline ============================
#define QH_F   0
#define QL_F   8704
#define PH2_F  17408
#define PL2_F  34816
#define QP_F   0
#define KV_F   34816
#define SQN_F  53248
#define KSUM_F 53376
#define ZP0_F  53632
#define ZP1_F  53760
#define TMP_F  53888
#define K2_FLOATS 54144
#define K2_SMEM (K2_FLOATS*4)
#define QPSTR 260
#define KVSTR 72

__global__ void __launch_bounds__(256, 1)
k2_out(const float* __restrict__ qg, float* __restrict__ outg) {
    extern __shared__ float smf[];
    const int t = threadIdx.x;
    const int lane = t & 31, w = t >> 5;
    const int g = lane >> 2, tig = lane & 3;
    const int bh = blockIdx.x >> 6, tile = blockIdx.x & 63;
    const int l0 = tile * 128;
    const size_t gbase = (size_t)bh * L_ * D_;

    // ---- load P hi/lo into padded smem ----
    {
        const float4* sh = (const float4*)g_Ph;
        const float4* sl = (const float4*)g_Pl;
#pragma unroll
        for (int i = 0; i < 16; i++) {
            int id = t + i * 256;
            int r = id >> 4, c4 = id & 15;
            *(float4*)(smf + PH2_F + r*QSTR + c4*4) = sh[id];
            *(float4*)(smf + PL2_F + r*QSTR + c4*4) = sl[id];
        }
    }
    // ---- load q tile, scale, split, sqn partials ----
    {
        const int r = t >> 1, c0 = (t & 1) * 32;
        const float4* src = (const float4*)(qg + gbase + (size_t)(l0 + r)*D_ + c0);
        float ss = 0.f;
#pragma unroll
        for (int i = 0; i < 8; i++) {
            float4 x = src[i];
            x.x *= NORMV; x.y *= NORMV; x.z *= NORMV; x.w *= NORMV;
            ss += x.x*x.x + x.y*x.y + x.z*x.z + x.w*x.w;
            float4 hv, lv;
            hv.x = tf32r(x.x); lv.x = tf32r(x.x - hv.x);
            hv.y = tf32r(x.y); lv.y = tf32r(x.y - hv.y);
            hv.z = tf32r(x.z); lv.z = tf32r(x.z - hv.z);
            hv.w = tf32r(x.w); lv.w = tf32r(x.w - hv.w);
            *(float4*)(smf + QH_F + r*QSTR + c0 + i*4) = hv;
            *(float4*)(smf + QL_F + r*QSTR + c0 + i*4) = lv;
        }
        smf[TMP_F + t] = ss;
    }
    smf[KSUM_F + t] = g_ksum[bh*M_ + t];
    __syncthreads();
    if (t < 128) smf[SQN_F + t] = 0.5f * (smf[TMP_F + 2*t] + smf[TMP_F + 2*t + 1]);
    __syncthreads();

    // ---- GEMM1: proj[128,256] = (qh+ql) @ (Ph+Pl)^T, 3 products ----
    const int lbase = (w & 3) * 32;
    const int n0base = (w >> 2) * 128;
    float acc[2][16][4];
#pragma unroll
    for (int lt = 0; lt < 2; lt++)
#pragma unroll
        for (int nt = 0; nt < 16; nt++)
#pragma unroll
            for (int i = 0; i < 4; i++) acc[lt][nt][i] = 0.f;

    for (int k8 = 0; k8 < 8; k8++) {
        const int k0 = k8 * 8;
        u32 ah[2][4], al[2][4];
#pragma unroll
        for (int lt = 0; lt < 2; lt++) {
            const int r0 = lbase + lt*16 + g;
            ah[lt][0] = f2u(smf[QH_F + r0*QSTR + k0 + tig]);
            ah[lt][1] = f2u(smf[QH_F + (r0+8)*QSTR + k0 + tig]);
            ah[lt][2] = f2u(smf[QH_F + r0*QSTR + k0 + tig + 4]);
            ah[lt][3] = f2u(smf[QH_F + (r0+8)*QSTR + k0 + tig + 4]);
            al[lt][0] = f2u(smf[QL_F + r0*QSTR + k0 + tig]);
            al[lt][1] = f2u(smf[QL_F + (r0+8)*QSTR + k0 + tig]);
            al[lt][2] = f2u(smf[QL_F + r0*QSTR + k0 + tig + 4]);
            al[lt][3] = f2u(smf[QL_F + (r0+8)*QSTR + k0 + tig + 4]);
        }
#pragma unroll
        for (int nt = 0; nt < 16; nt++) {
            const int n0 = n0base + nt*8;
            u32 bh0 = f2u(smf[PH2_F + (n0+g)*QSTR + k0 + tig]);
            u32 bh1 = f2u(smf[PH2_F + (n0+g)*QSTR + k0 + tig + 4]);
            u32 bl0 = f2u(smf[PL2_F + (n0+g)*QSTR + k0 + tig]);
            u32 bl1 = f2u(smf[PL2_F + (n0+g)*QSTR + k0 + tig + 4]);
#pragma unroll
            for (int lt = 0; lt < 2; lt++) {
                mma8(acc[lt][nt], ah[lt], bh0, bh1);
                mma8(acc[lt][nt], ah[lt], bl0, bl1);
                mma8(acc[lt][nt], al[lt], bh0, bh1);
            }
        }
    }
    __syncthreads();

    // ---- Epilogue 1: exp, z-dot, tf32 round, store q' ----
#pragma unroll
    for (int lt = 0; lt < 2; lt++) {
        const int r1 = lbase + lt*16 + g;
        const int r2 = r1 + 8;
        const float sq1 = smf[SQN_F + r1], sq2 = smf[SQN_F + r2];
        float za1 = 0.f, za2 = 0.f;
#pragma unroll
        for (int nt = 0; nt < 16; nt++) {
            const int n = n0base + nt*8 + 2*tig;
            const float ks0 = smf[KSUM_F + n], ks1 = smf[KSUM_F + n + 1];
            float e00 = __expf(acc[lt][nt][0] - sq1 + EPSK);
            float e01 = __expf(acc[lt][nt][1] - sq1 + EPSK);
            float e10 = __expf(acc[lt][nt][2] - sq2 + EPSK);
            float e11 = __expf(acc[lt][nt][3] - sq2 + EPSK);
            za1 += e00*ks0 + e01*ks1;
            za2 += e10*ks0 + e11*ks1;
            *(float2*)(smf + QP_F + r1*QPSTR + n) = make_float2(tf32r(e00), tf32r(e01));
            *(float2*)(smf + QP_F + r2*QPSTR + n) = make_float2(tf32r(e10), tf32r(e11));
        }
        za1 += __shfl_xor_sync(0xffffffffu, za1, 1);
        za1 += __shfl_xor_sync(0xffffffffu, za1, 2);
        za2 += __shfl_xor_sync(0xffffffffu, za2, 1);
        za2 += __shfl_xor_sync(0xffffffffu, za2, 2);
        if (tig == 0) {
            float* zp = smf + ((w >> 2) ? ZP1_F : ZP0_F);
            zp[r1] = za1;
            zp[r2] = za2;
        }
    }
    // ---- load kv (tf32-rounded) into stride-72 smem ----
    {
        const float4* src = (const float4*)(g_kv + (size_t)bh * M_ * D_);
#pragma unroll
        for (int i = 0; i < 16; i++) {
            int id = t + i * 256;
            int m = id >> 4, c4 = id & 15;
            *(float4*)(smf + KV_F + m*KVSTR + c4*4) = src[id];
        }
    }
    __syncthreads();

    // ---- GEMM2: out[128,64] = q'[128,256] @ kv[256,64] ----
    const int r0 = w*16 + g;
    float acc2[8][4];
#pragma unroll
    for (int nt = 0; nt < 8; nt++)
#pragma unroll
        for (int i = 0; i < 4; i++) acc2[nt][i] = 0.f;

#pragma unroll 2
    for (int km = 0; km < 32; km++) {
        const int m0 = km * 8;
        u32 a[4];
        a[0] = f2u(smf[QP_F + r0*QPSTR + m0 + tig]);
        a[1] = f2u(smf[QP_F + (r0+8)*QPSTR + m0 + tig]);
        a[2] = f2u(smf[QP_F + r0*QPSTR + m0 + tig + 4]);
        a[3] = f2u(smf[QP_F + (r0+8)*QPSTR + m0 + tig + 4]);
#pragma unroll
        for (int nt = 0; nt < 8; nt++) {
            u32 b0 = f2u(smf[KV_F + (m0+tig)*KVSTR + nt*8 + g]);
            u32 b1 = f2u(smf[KV_F + (m0+tig+4)*KVSTR + nt*8 + g]);
            mma8(acc2[nt], a, b0, b1);
        }
    }

    // ---- Epilogue 2: scale by z, store ----
    {
        const float z1 = 1.0f / (smf[ZP0_F + r0] + smf[ZP1_F + r0] + EPSZ);
        const float z2 = 1.0f / (smf[ZP0_F + r0 + 8] + smf[ZP1_F + r0 + 8] + EPSZ);
        float* o1 = outg + gbase + (size_t)(l0 + r0)*D_;
        float* o2 = outg + gbase + (size_t)(l0 + r0 + 8)*D_;
#pragma unroll
        for (int nt = 0; nt < 8; nt++) {
            const int d = nt*8 + 2*tig;
            *(float2*)(o1 + d) = make_float2(acc2[nt][0]*z1, acc2[nt][1]*z1);
            *(float2*)(o2 + d) = make_float2(acc2[nt][2]*z2, acc2[nt][3]*z2);
        }
    }
}

extern "C" void kernel_launch(void* const* d_in, const int* in_sizes, int n_in,
                              void* d_out, int out_size) {
    (void)in_sizes; (void)n_in; (void)out_size;
    const float* q = (const float*)d_in[0];
    const float* k = (const float*)d_in[1];
    const float* v = (const float*)d_in[2];
    const float* P = (const float*)d_in[3];
    float* out = (float*)d_out;

    cudaFuncSetAttribute(k1_mma, cudaFuncAttributeMaxDynamicSharedMemorySize, K1_SMEM);
    cudaFuncSetAttribute(k2_out, cudaFuncAttributeMaxDynamicSharedMemorySize, K2_SMEM);

    k_prep_P<<<64, 256>>>(P);
    k1_mma<<<BH_*CH2, 256, K1_SMEM>>>(k, v);
    k_reduce<<<(BH_*PART_SZ)/256, 256>>>();
    k2_out<<<BH_*CH2, 256, K2_SMEM>>>(q, out);
}

// round 10
// speedup vs baseline: 3.2909x; 1.0067x over previous
#include <cuda_runtime.h>
#include <cstdint>

typedef unsigned int u32;

#define B_ 4
#define H_ 8
#define L_ 8192
#define D_ 64
#define M_ 256
#define BH_ (B_*H_)
#define CH2 64                              // 64 chunks of 128 l-rows
#define NORMV 0.35355339059327373f          // 64^(-1/4)
#define EPSK 1e-6f
#define EPSZ 1e-6f
#define NT 512

#define PART_SZ (M_*D_ + M_)                // 16640 floats per partial

__device__ __align__(16) float g_part[BH_*CH2*PART_SZ];   // ~136 MB
__device__ __align__(16) float g_kv[BH_*M_*D_];           // tf32-rounded
__device__ __align__(16) float g_ksum[BH_*M_];            // fp32
__device__ __align__(16) float g_Ph[M_*D_];               // tf32 hi
__device__ __align__(16) float g_Pl[M_*D_];               // tf32 lo

// ---- tf32 / mma helpers ----
__device__ __forceinline__ float tf32r(float x) {
    u32 u; asm("cvt.rna.tf32.f32 %0, %1;" : "=r"(u) : "f"(x));
    return __uint_as_float(u);
}
__device__ __forceinline__ u32 f2u(float x) { return __float_as_uint(x); }
__device__ __forceinline__ void mma8(float* c, const u32* a, u32 b0, u32 b1) {
    asm volatile(
        "mma.sync.aligned.m16n8k8.row.col.f32.tf32.tf32.f32 "
        "{%0,%1,%2,%3}, {%4,%5,%6,%7}, {%8,%9}, {%0,%1,%2,%3};"
        : "+f"(c[0]), "+f"(c[1]), "+f"(c[2]), "+f"(c[3])
        : "r"(a[0]), "r"(a[1]), "r"(a[2]), "r"(a[3]), "r"(b0), "r"(b1));
}

// ================== prep: P -> tf32 hi/lo split (plain [m][d]) ==================

__global__ void k_prep_P(const float* __restrict__ Pg) {
    int idx = blockIdx.x * 256 + threadIdx.x;   // 16384
    float x = Pg[idx];
    float hi = tf32r(x);
    float lo = tf32r(x - hi);
    g_Ph[idx] = hi;
    g_Pl[idx] = lo;
}

// ============================ k1: mma.sync tf32 (512 thr) ============================
// smem float offsets:
//  phase A: KH@0 (128*68=8704), KL@8704, PH@17408 (256*68), PL@34816 (ends 52224)
//  phase B (aliases A): qpT@0 (256*132=33792), V@33792 (128*72=9216)
//  tail: SQN1@52224(128) TMP1@52352(512) PKS@52864(16*64=1024) -> 53888 floats
#define KH_F   0
#define KL_F   8704
#define PH_F   17408
#define PL_F   34816
#define QPT_F  0
#define V_F    33792
#define SQN1_F 52224
#define TMP1_F 52352
#define PKS_F  52864
#define K1_FLOATS 53888
#define K1_SMEM (K1_FLOATS*4)
#define QSTR 68
#define QPT_STR 132
#define VSTR 72

__global__ void __launch_bounds__(NT, 1)
k1_mma(const float* __restrict__ kg, const float* __restrict__ vg) {
    extern __shared__ float smf[];
    const int t = threadIdx.x;
    const int lane = t & 31, w = t >> 5;      // 16 warps
    const int g = lane >> 2, tig = lane & 3;
    const int bh = blockIdx.x >> 6, tile = blockIdx.x & 63;
    const int l0 = tile * 128;
    const size_t gbase = (size_t)bh * L_ * D_;

    // ---- load P hi/lo into padded smem ----
    {
        const float4* sh = (const float4*)g_Ph;
        const float4* sl = (const float4*)g_Pl;
#pragma unroll
        for (int i = 0; i < 8; i++) {
            int id = t + i * NT;               // 4096 float4
            int r = id >> 4, c4 = id & 15;
            *(float4*)(smf + PH_F + r*QSTR + c4*4) = sh[id];
            *(float4*)(smf + PL_F + r*QSTR + c4*4) = sl[id];
        }
    }
    // ---- load k tile, scale, split, sqn partials ----
    {
        const int r = t >> 2, c0 = (t & 3) * 16;
        const float4* src = (const float4*)(kg + gbase + (size_t)(l0 + r)*D_ + c0);
        float ss = 0.f;
#pragma unroll
        for (int i = 0; i < 4; i++) {
            float4 x = src[i];
            x.x *= NORMV; x.y *= NORMV; x.z *= NORMV; x.w *= NORMV;
            ss += x.x*x.x + x.y*x.y + x.z*x.z + x.w*x.w;
            float4 hv, lv;
            hv.x = tf32r(x.x); lv.x = tf32r(x.x - hv.x);
            hv.y = tf32r(x.y); lv.y = tf32r(x.y - hv.y);
            hv.z = tf32r(x.z); lv.z = tf32r(x.z - hv.z);
            hv.w = tf32r(x.w); lv.w = tf32r(x.w - hv.w);
            *(float4*)(smf + KH_F + r*QSTR + c0 + i*4) = hv;
            *(float4*)(smf + KL_F + r*QSTR + c0 + i*4) = lv;
        }
        smf[TMP1_F + t] = ss;
    }
    __syncthreads();
    if (t < 128) {
        smf[SQN1_F + t] = 0.5f * (smf[TMP1_F + 4*t] + smf[TMP1_F + 4*t+1]
                                + smf[TMP1_F + 4*t+2] + smf[TMP1_F + 4*t+3]);
    }
    __syncthreads();

    // ---- GEMM1: proj[128,256] = (kh+kl) @ (Ph+Pl)^T, warp grid 4x4, 32x64/warp ----
    const int lbase = (w & 3) * 32;
    const int n0base = (w >> 2) * 64;
    float acc[2][8][4];
#pragma unroll
    for (int lt = 0; lt < 2; lt++)
#pragma unroll
        for (int nt = 0; nt < 8; nt++)
#pragma unroll
            for (int i = 0; i < 4; i++) acc[lt][nt][i] = 0.f;

    for (int k8 = 0; k8 < 8; k8++) {
        const int k0 = k8 * 8;
        u32 ah[2][4], al[2][4];
#pragma unroll
        for (int lt = 0; lt < 2; lt++) {
            const int r0 = lbase + lt*16 + g;
            ah[lt][0] = f2u(smf[KH_F + r0*QSTR + k0 + tig]);
            ah[lt][1] = f2u(smf[KH_F + (r0+8)*QSTR + k0 + tig]);
            ah[lt][2] = f2u(smf[KH_F + r0*QSTR + k0 + tig + 4]);
            ah[lt][3] = f2u(smf[KH_F + (r0+8)*QSTR + k0 + tig + 4]);
            al[lt][0] = f2u(smf[KL_F + r0*QSTR + k0 + tig]);
            al[lt][1] = f2u(smf[KL_F + (r0+8)*QSTR + k0 + tig]);
            al[lt][2] = f2u(smf[KL_F + r0*QSTR + k0 + tig + 4]);
            al[lt][3] = f2u(smf[KL_F + (r0+8)*QSTR + k0 + tig + 4]);
        }
#pragma unroll
        for (int nt = 0; nt < 8; nt++) {
            const int n0 = n0base + nt*8;
            u32 bh0 = f2u(smf[PH_F + (n0+g)*QSTR + k0 + tig]);
            u32 bh1 = f2u(smf[PH_F + (n0+g)*QSTR + k0 + tig + 4]);
            u32 bl0 = f2u(smf[PL_F + (n0+g)*QSTR + k0 + tig]);
            u32 bl1 = f2u(smf[PL_F + (n0+g)*QSTR + k0 + tig + 4]);
#pragma unroll
            for (int lt = 0; lt < 2; lt++) {
                mma8(acc[lt][nt], ah[lt], bh0, bh1);
                mma8(acc[lt][nt], ah[lt], bl0, bl1);
                mma8(acc[lt][nt], al[lt], bh0, bh1);
            }
        }
    }
    __syncthreads();   // all warps done reading KH/KL/PH/PL

    // ---- Epilogue 1: exp, tf32 store TRANSPOSED qpT[m][l], ksum from registers ----
    {
        float sqa[2][2];
#pragma unroll
        for (int lt = 0; lt < 2; lt++) {
            const int r1 = lbase + lt*16 + g;
            sqa[lt][0] = smf[SQN1_F + r1];
            sqa[lt][1] = smf[SQN1_F + r1 + 8];
        }
#pragma unroll
        for (int nt = 0; nt < 8; nt++) {
            const int n = n0base + nt*8 + 2*tig;
            float cs0 = 0.f, cs1 = 0.f;
#pragma unroll
            for (int lt = 0; lt < 2; lt++) {
                const int r1 = lbase + lt*16 + g;
                const int r2 = r1 + 8;
                float e00 = __expf(acc[lt][nt][0] - sqa[lt][0] + EPSK);
                float e01 = __expf(acc[lt][nt][1] - sqa[lt][0] + EPSK);
                float e10 = __expf(acc[lt][nt][2] - sqa[lt][1] + EPSK);
                float e11 = __expf(acc[lt][nt][3] - sqa[lt][1] + EPSK);
                cs0 += e00 + e10;
                cs1 += e01 + e11;
                smf[QPT_F + n*QPT_STR + r1]     = tf32r(e00);
                smf[QPT_F + (n+1)*QPT_STR + r1] = tf32r(e01);
                smf[QPT_F + n*QPT_STR + r2]     = tf32r(e10);
                smf[QPT_F + (n+1)*QPT_STR + r2] = tf32r(e11);
            }
            cs0 += __shfl_xor_sync(0xffffffffu, cs0, 4);
            cs0 += __shfl_xor_sync(0xffffffffu, cs0, 8);
            cs0 += __shfl_xor_sync(0xffffffffu, cs0, 16);
            cs1 += __shfl_xor_sync(0xffffffffu, cs1, 4);
            cs1 += __shfl_xor_sync(0xffffffffu, cs1, 8);
            cs1 += __shfl_xor_sync(0xffffffffu, cs1, 16);
            if (lane < 4) {
                smf[PKS_F + w*64 + nt*8 + 2*tig]     = cs0;
                smf[PKS_F + w*64 + nt*8 + 2*tig + 1] = cs1;
            }
        }
    }
    // ---- load v tile (tf32-rounded) into stride-72 smem ----
    {
        const float4* src = (const float4*)(vg + gbase + (size_t)l0*D_);
#pragma unroll
        for (int i = 0; i < 4; i++) {
            int id = t + i * NT;               // 2048 float4
            int l = id >> 4, c4 = id & 15;
            float4 x = src[id];
            x.x = tf32r(x.x); x.y = tf32r(x.y); x.z = tf32r(x.z); x.w = tf32r(x.w);
            *(float4*)(smf + V_F + l*VSTR + c4*4) = x;
        }
    }
    __syncthreads();

    // ---- GEMM2: kv_partial[256,64] = qpT[256,128] @ v[128,64]; 16 m-rows/warp ----
    const int m0 = w * 16;
    float acc2[8][4];
#pragma unroll
    for (int nt = 0; nt < 8; nt++)
#pragma unroll
        for (int i = 0; i < 4; i++) acc2[nt][i] = 0.f;

    for (int k8 = 0; k8 < 16; k8++) {
        const int lk = k8 * 8;
        u32 a[4];
        a[0] = f2u(smf[QPT_F + (m0+g)*QPT_STR + lk + tig]);
        a[1] = f2u(smf[QPT_F + (m0+8+g)*QPT_STR + lk + tig]);
        a[2] = f2u(smf[QPT_F + (m0+g)*QPT_STR + lk + tig + 4]);
        a[3] = f2u(smf[QPT_F + (m0+8+g)*QPT_STR + lk + tig + 4]);
#pragma unroll
        for (int nt = 0; nt < 8; nt++) {
            u32 b0 = f2u(smf[V_F + (lk+tig)*VSTR + nt*8 + g]);
            u32 b1 = f2u(smf[V_F + (lk+tig+4)*VSTR + nt*8 + g]);
            mma8(acc2[nt], a, b0, b1);
        }
    }

    // ---- write kv partial + ksum partial ----
    float* pb = g_part + (size_t)(bh*CH2 + tile) * PART_SZ;
    {
        const int r1 = m0 + g, r2 = r1 + 8;
#pragma unroll
        for (int nt = 0; nt < 8; nt++) {
            const int d = nt*8 + 2*tig;
            *(float2*)(pb + r1*D_ + d) = make_float2(acc2[nt][0], acc2[nt][1]);
            *(float2*)(pb + r2*D_ + d) = make_float2(acc2[nt][2], acc2[nt][3]);
        }
    }
    // ksum: column n gets partials from warps 4*(n>>6)+r, r=0..3
    if (t < M_) {
        const int wb = (t >> 6) * 4, nloc = t & 63;
        float s = smf[PKS_F + (wb+0)*64 + nloc]
                + smf[PKS_F + (wb+1)*64 + nloc]
                + smf[PKS_F + (wb+2)*64 + nloc]
                + smf[PKS_F + (wb+3)*64 + nloc];
        pb[M_*D_ + t] = s;
    }
}

// ========== reduce: partials -> ksum fp32, kv tf32-rounded fp32 ==========

__global__ void k_reduce() {
    int idx = blockIdx.x * 256 + threadIdx.x;
    int bh = idx / PART_SZ;
    int r  = idx - bh * PART_SZ;
    const float* p = g_part + (size_t)bh * CH2 * PART_SZ + r;
    float s = 0.f;
#pragma unroll
    for (int c = 0; c < CH2; c++) s += p[(size_t)c * PART_SZ];
    if (r < M_*D_) g_kv[bh*M_*D_ + r] = tf32r(s);
    else           g_ksum[bh*M_ + (r - M_*D_)] = s;
}

// ============================ k2: mma.sync tf32 (512 thr) ============================
// phase A: QH@0, QL@8704, PH2@17408, PL2@34816 (ends 52224)
// phase B: QP@0 (128*260=33280), KV@34816 (256*72=18432, ends 53248)
// tail: SQN@53248(128) KSUM@53376(256) ZP@53632(512) TMP@54144(512) -> 54656 floats
#define QH_F   0
#define QL_F   8704
#define PH2_F  17408
#define PL2_F  34816
#define QP_F   0
#define KV_F   34816
#define SQN_F  53248
#define KSUM_F 53376
#define ZP_F   53632
#define TMP_F  54144
#define K2_FLOATS 54656
#define K2_SMEM (K2_FLOATS*4)
#define QPSTR 260
#define KVSTR 72

__global__ void __launch_bounds__(NT, 1)
k2_out(const float* __restrict__ qg, float* __restrict__ outg) {
    extern __shared__ float smf[];
    const int t = threadIdx.x;
    const int lane = t & 31, w = t >> 5;      // 16 warps
    const int g = lane >> 2, tig = lane & 3;
    const int bh = blockIdx.x >> 6, tile = blockIdx.x & 63;
    const int l0 = tile * 128;
    const size_t gbase = (size_t)bh * L_ * D_;

    // ---- load P hi/lo ----
    {
        const float4* sh = (const float4*)g_Ph;
        const float4* sl = (const float4*)g_Pl;
#pragma unroll
        for (int i = 0; i < 8; i++) {
            int id = t + i * NT;
            int r = id >> 4, c4 = id & 15;
            *(float4*)(smf + PH2_F + r*QSTR + c4*4) = sh[id];
            *(float4*)(smf + PL2_F + r*QSTR + c4*4) = sl[id];
        }
    }
    // ---- load q tile, scale, split, sqn partials ----
    {
        const int r = t >> 2, c0 = (t & 3) * 16;
        const float4* src = (const float4*)(qg + gbase + (size_t)(l0 + r)*D_ + c0);
        float ss = 0.f;
#pragma unroll
        for (int i = 0; i < 4; i++) {
            float4 x = src[i];
            x.x *= NORMV; x.y *= NORMV; x.z *= NORMV; x.w *= NORMV;
            ss += x.x*x.x + x.y*x.y + x.z*x.z + x.w*x.w;
            float4 hv, lv;
            hv.x = tf32r(x.x); lv.x = tf32r(x.x - hv.x);
            hv.y = tf32r(x.y); lv.y = tf32r(x.y - hv.y);
            hv.z = tf32r(x.z); lv.z = tf32r(x.z - hv.z);
            hv.w = tf32r(x.w); lv.w = tf32r(x.w - hv.w);
            *(float4*)(smf + QH_F + r*QSTR + c0 + i*4) = hv;
            *(float4*)(smf + QL_F + r*QSTR + c0 + i*4) = lv;
        }
        smf[TMP_F + t] = ss;
    }
    if (t < M_) smf[KSUM_F + t] = g_ksum[bh*M_ + t];
    __syncthreads();
    if (t < 128) {
        smf[SQN_F + t] = 0.5f * (smf[TMP_F + 4*t] + smf[TMP_F + 4*t+1]
                               + smf[TMP_F + 4*t+2] + smf[TMP_F + 4*t+3]);
    }
    __syncthreads();

    // ---- GEMM1: proj[128,256], warp grid 4x4, 32x64/warp ----
    const int lbase = (w & 3) * 32;
    const int n0base = (w >> 2) * 64;
    float acc[2][8][4];
#pragma unroll
    for (int lt = 0; lt < 2; lt++)
#pragma unroll
        for (int nt = 0; nt < 8; nt++)
#pragma unroll
            for (int i = 0; i < 4; i++) acc[lt][nt][i] = 0.f;

    for (int k8 = 0; k8 < 8; k8++) {
        const int k0 = k8 * 8;
        u32 ah[2][4], al[2][4];
#pragma unroll
        for (int lt = 0; lt < 2; lt++) {
            const int r0 = lbase + lt*16 + g;
            ah[lt][0] = f2u(smf[QH_F + r0*QSTR + k0 + tig]);
            ah[lt][1] = f2u(smf[QH_F + (r0+8)*QSTR + k0 + tig]);
            ah[lt][2] = f2u(smf[QH_F + r0*QSTR + k0 + tig + 4]);
            ah[lt][3] = f2u(smf[QH_F + (r0+8)*QSTR + k0 + tig + 4]);
            al[lt][0] = f2u(smf[QL_F + r0*QSTR + k0 + tig]);
            al[lt][1] = f2u(smf[QL_F + (r0+8)*QSTR + k0 + tig]);
            al[lt][2] = f2u(smf[QL_F + r0*QSTR + k0 + tig + 4]);
            al[lt][3] = f2u(smf[QL_F + (r0+8)*QSTR + k0 + tig + 4]);
        }
#pragma unroll
        for (int nt = 0; nt < 8; nt++) {
            const int n0 = n0base + nt*8;
            u32 bh0 = f2u(smf[PH2_F + (n0+g)*QSTR + k0 + tig]);
            u32 bh1 = f2u(smf[PH2_F + (n0+g)*QSTR + k0 + tig + 4]);
            u32 bl0 = f2u(smf[PL2_F + (n0+g)*QSTR + k0 + tig]);
            u32 bl1 = f2u(smf[PL2_F + (n0+g)*QSTR + k0 + tig + 4]);
#pragma unroll
            for (int lt = 0; lt < 2; lt++) {
                mma8(acc[lt][nt], ah[lt], bh0, bh1);
                mma8(acc[lt][nt], ah[lt], bl0, bl1);
                mma8(acc[lt][nt], al[lt], bh0, bh1);
            }
        }
    }
    __syncthreads();

    // ---- Epilogue 1: exp, z-dot, tf32 round, store q' ----
#pragma unroll
    for (int lt = 0; lt < 2; lt++) {
        const int r1 = lbase + lt*16 + g;
        const int r2 = r1 + 8;
        const float sq1 = smf[SQN_F + r1], sq2 = smf[SQN_F + r2];
        float za1 = 0.f, za2 = 0.f;
#pragma unroll
        for (int nt = 0; nt < 8; nt++) {
            const int n = n0base + nt*8 + 2*tig;
            const float ks0 = smf[KSUM_F + n], ks1 = smf[KSUM_F + n + 1];
            float e00 = __expf(acc[lt][nt][0] - sq1 + EPSK);
            float e01 = __expf(acc[lt][nt][1] - sq1 + EPSK);
            float e10 = __expf(acc[lt][nt][2] - sq2 + EPSK);
            float e11 = __expf(acc[lt][nt][3] - sq2 + EPSK);
            za1 += e00*ks0 + e01*ks1;
            za2 += e10*ks0 + e11*ks1;
            *(float2*)(smf + QP_F + r1*QPSTR + n) = make_float2(tf32r(e00), tf32r(e01));
            *(float2*)(smf + QP_F + r2*QPSTR + n) = make_float2(tf32r(e10), tf32r(e11));
        }
        za1 += __shfl_xor_sync(0xffffffffu, za1, 1);
        za1 += __shfl_xor_sync(0xffffffffu, za1, 2);
        za2 += __shfl_xor_sync(0xffffffffu, za2, 1);
        za2 += __shfl_xor_sync(0xffffffffu, za2, 2);
        if (tig == 0) {
            float* zp = smf + ZP_F + (w >> 2) * 128;
            zp[r1] = za1;
            zp[r2] = za2;
        }
    }
    // ---- load kv (tf32-rounded) into stride-72 smem ----
    {
        const float4* src = (const float4*)(g_kv + (size_t)bh * M_ * D_);
#pragma unroll
        for (int i = 0; i < 8; i++) {
            int id = t + i * NT;
            int m = id >> 4, c4 = id & 15;
            *(float4*)(smf + KV_F + m*KVSTR + c4*4) = src[id];
        }
    }
    __syncthreads();

    // ---- GEMM2: out[128,64] = q'[128,256] @ kv[256,64]; warp grid 8x2 ----
    const int r0 = (w & 7)*16 + g;
    const int colbase = (w >> 3) * 32;
    float acc2[4][4];
#pragma unroll
    for (int nt = 0; nt < 4; nt++)
#pragma unroll
        for (int i = 0; i < 4; i++) acc2[nt][i] = 0.f;

    for (int km = 0; km < 32; km++) {
        const int m0 = km * 8;
        u32 a[4];
        a[0] = f2u(smf[QP_F + r0*QPSTR + m0 + tig]);
        a[1] = f2u(smf[QP_F + (r0+8)*QPSTR + m0 + tig]);
        a[2] = f2u(smf[QP_F + r0*QPSTR + m0 + tig + 4]);
        a[3] = f2u(smf[QP_F + (r0+8)*QPSTR + m0 + tig + 4]);
#pragma unroll
        for (int nt = 0; nt < 4; nt++) {
            u32 b0 = f2u(smf[KV_F + (m0+tig)*KVSTR + colbase + nt*8 + g]);
            u32 b1 = f2u(smf[KV_F + (m0+tig+4)*KVSTR + colbase + nt*8 + g]);
            mma8(acc2[nt], a, b0, b1);
        }
    }

    // ---- Epilogue 2: scale by z (sum of 4 group partials), store ----
    {
        const float* zp = smf + ZP_F;
        const float z1 = 1.0f / (zp[r0] + zp[128 + r0] + zp[256 + r0] + zp[384 + r0] + EPSZ);
        const float z2 = 1.0f / (zp[r0+8] + zp[128 + r0+8] + zp[256 + r0+8] + zp[384 + r0+8] + EPSZ);
        float* o1 = outg + gbase + (size_t)(l0 + r0)*D_ + colbase;
        float* o2 = outg + gbase + (size_t)(l0 + r0 + 8)*D_ + colbase;
#pragma unroll
        for (int nt = 0; nt < 4; nt++) {
            const int d = nt*8 + 2*tig;
            *(float2*)(o1 + d) = make_float2(acc2[nt][0]*z1, acc2[nt][1]*z1);
            *(float2*)(o2 + d) = make_float2(acc2[nt][2]*z2, acc2[nt][3]*z2);
        }
    }
}

extern "C" void kernel_launch(void* const* d_in, const int* in_sizes, int n_in,
                              void* d_out, int out_size) {
    (void)in_sizes; (void)n_in; (void)out_size;
    const float* q = (const float*)d_in[0];
    const float* k = (const float*)d_in[1];
    const float* v = (const float*)d_in[2];
    const float* P = (const float*)d_in[3];
    float* out = (float*)d_out;

    cudaFuncSetAttribute(k1_mma, cudaFuncAttributeMaxDynamicSharedMemorySize, K1_SMEM);
    cudaFuncSetAttribute(k2_out, cudaFuncAttributeMaxDynamicSharedMemorySize, K2_SMEM);

    k_prep_P<<<64, 256>>>(P);
    k1_mma<<<BH_*CH2, NT, K1_SMEM>>>(k, v);
    k_reduce<<<(BH_*PART_SZ)/256, 256>>>();
    k2_out<<<BH_*CH2, NT, K2_SMEM>>>(q, out);
}

// round 11
// speedup vs baseline: 4.4645x; 1.3566x over previous
#include <cuda_runtime.h>
#include <cuda_bf16.h>
#include <cstdint>

typedef unsigned int u32;

#define B_ 4
#define H_ 8
#define L_ 8192
#define D_ 64
#define M_ 256
#define BH_ (B_*H_)
#define CH2 64                              // 64 chunks of 128 l-rows
#define NORMV 0.35355339059327373f          // 64^(-1/4)
#define EPSK 1e-6f
#define EPSZ 1e-6f
#define NT 512

#define PART_SZ (M_*D_ + M_)                // 16640 floats per partial

__device__ __align__(16) float g_part[BH_*CH2*PART_SZ];   // ~136 MB
__device__ __align__(16) float g_kv[BH_*M_*D_];           // tf32-rounded
__device__ __align__(16) float g_ksum[BH_*M_];            // fp32
__device__ __align__(16) u32 g_Pbh[M_*D_/2];              // bf16-hi pairs
__device__ __align__(16) u32 g_Pbl[M_*D_/2];              // bf16-lo pairs

// ---- tf32 / bf16 / mma helpers ----
__device__ __forceinline__ float tf32r(float x) {
    u32 u; asm("cvt.rna.tf32.f32 %0, %1;" : "=r"(u) : "f"(x));
    return __uint_as_float(u);
}
__device__ __forceinline__ u32 f2u(float x) { return __float_as_uint(x); }
__device__ __forceinline__ u32 bpack(__nv_bfloat16 a, __nv_bfloat16 b) {
    unsigned short ua = *(unsigned short*)&a, ub = *(unsigned short*)&b;
    return (u32)ua | ((u32)ub << 16);        // low half = first (even-k) element
}
__device__ __forceinline__ void bsplit2(float a, float b, u32 &hi, u32 &lo) {
    __nv_bfloat16 ha = __float2bfloat16(a), hb = __float2bfloat16(b);
    float ra = a - __bfloat162float(ha);
    float rb = b - __bfloat162float(hb);
    hi = bpack(ha, hb);
    lo = bpack(__float2bfloat16(ra), __float2bfloat16(rb));
}
// tf32 m16n8k8 (GEMM2, unchanged)
__device__ __forceinline__ void mma8(float* c, const u32* a, u32 b0, u32 b1) {
    asm volatile(
        "mma.sync.aligned.m16n8k8.row.col.f32.tf32.tf32.f32 "
        "{%0,%1,%2,%3}, {%4,%5,%6,%7}, {%8,%9}, {%0,%1,%2,%3};"
        : "+f"(c[0]), "+f"(c[1]), "+f"(c[2]), "+f"(c[3])
        : "r"(a[0]), "r"(a[1]), "r"(a[2]), "r"(a[3]), "r"(b0), "r"(b1));
}
// bf16 m16n8k16 (GEMM1)
__device__ __forceinline__ void mma16(float* c, const u32* a, u32 b0, u32 b1) {
    asm volatile(
        "mma.sync.aligned.m16n8k16.row.col.f32.bf16.bf16.f32 "
        "{%0,%1,%2,%3}, {%4,%5,%6,%7}, {%8,%9}, {%0,%1,%2,%3};"
        : "+f"(c[0]), "+f"(c[1]), "+f"(c[2]), "+f"(c[3])
        : "r"(a[0]), "r"(a[1]), "r"(a[2]), "r"(a[3]), "r"(b0), "r"(b1));
}

// ========== prep: P -> bf16 hi/lo split pairs (plain [m][d]) ==========

__global__ void k_prep_P(const float* __restrict__ Pg) {
    int idx = blockIdx.x * 256 + threadIdx.x;   // 8192 pairs
    float x0 = Pg[2*idx], x1 = Pg[2*idx + 1];
    u32 hi, lo;
    bsplit2(x0, x1, hi, lo);
    g_Pbh[idx] = hi;
    g_Pbl[idx] = lo;
}

// ============================ k1: bf16-GEMM1 + tf32-GEMM2 ============================
// word/float offsets (1 word = 1 float = 4B):
//  phase A (bf16, u32 words): KHB@0 (128*36=4608), KLB@4608, PHB@9216 (256*36), PLB@18432 -> 27648
//  phase B (fp32, aliases A): qpT@0 (256*132=33792), V@33792 (128*72=9216) -> 43008
//  tail: SQN1@43008(128) TMP1@43136(512) PKS@43648(1024) -> 44672 floats
#define KHB_W  0
#define KLB_W  4608
#define PHB_W  9216
#define PLB_W  18432
#define QPT_F  0
#define V_F    33792
#define SQN1_F 43008
#define TMP1_F 43136
#define PKS_F  43648
#define K1_FLOATS 44672
#define K1_SMEM (K1_FLOATS*4)
#define BSTR 36                              // bf16 row stride in u32 words (72 bf16)
#define QPT_STR 132
#define VSTR 72

__global__ void __launch_bounds__(NT, 1)
k1_mma(const float* __restrict__ kg, const float* __restrict__ vg) {
    extern __shared__ float smf[];
    u32* smw = (u32*)smf;
    const int t = threadIdx.x;
    const int lane = t & 31, w = t >> 5;      // 16 warps
    const int g = lane >> 2, tig = lane & 3;
    const int bh = blockIdx.x >> 6, tile = blockIdx.x & 63;
    const int l0 = tile * 128;
    const size_t gbase = (size_t)bh * L_ * D_;

    // ---- copy P bf16 hi/lo into stride-36 smem ----
    {
        const uint4* sh = (const uint4*)g_Pbh;   // 2048 uint4
        const uint4* sl = (const uint4*)g_Pbl;
#pragma unroll
        for (int i = 0; i < 4; i++) {
            int id = t + i * NT;
            int m = id >> 3, j = id & 7;
            *(uint4*)(smw + PHB_W + m*BSTR + j*4) = sh[id];
            *(uint4*)(smw + PLB_W + m*BSTR + j*4) = sl[id];
        }
    }
    // ---- load k tile, scale, bf16 split, sqn partials ----
    {
        const int r = t >> 2, c0w = (t & 3) * 8;
        const float4* src = (const float4*)(kg + gbase + (size_t)(l0 + r)*D_ + (t & 3)*16);
        float ss = 0.f;
#pragma unroll
        for (int i = 0; i < 4; i++) {
            float4 x = src[i];
            x.x *= NORMV; x.y *= NORMV; x.z *= NORMV; x.w *= NORMV;
            ss += x.x*x.x + x.y*x.y + x.z*x.z + x.w*x.w;
            u32 h01, l01, h23, l23;
            bsplit2(x.x, x.y, h01, l01);
            bsplit2(x.z, x.w, h23, l23);
            *(uint2*)(smw + KHB_W + r*BSTR + c0w + 2*i) = make_uint2(h01, h23);
            *(uint2*)(smw + KLB_W + r*BSTR + c0w + 2*i) = make_uint2(l01, l23);
        }
        smf[TMP1_F + t] = ss;
    }
    __syncthreads();
    if (t < 128) {
        smf[SQN1_F + t] = 0.5f * (smf[TMP1_F + 4*t] + smf[TMP1_F + 4*t+1]
                                + smf[TMP1_F + 4*t+2] + smf[TMP1_F + 4*t+3]);
    }
    __syncthreads();

    // ---- GEMM1 (bf16 k16): proj[128,256], warp grid 4x4, 32x64/warp, 3 products ----
    const int lbase = (w & 3) * 32;
    const int n0base = (w >> 2) * 64;
    float acc[2][8][4];
#pragma unroll
    for (int lt = 0; lt < 2; lt++)
#pragma unroll
        for (int nt = 0; nt < 8; nt++)
#pragma unroll
            for (int i = 0; i < 4; i++) acc[lt][nt][i] = 0.f;

#pragma unroll
    for (int ks = 0; ks < 4; ks++) {
        const int k0w = ks * 8;
        u32 ah[2][4], al[2][4];
#pragma unroll
        for (int lt = 0; lt < 2; lt++) {
            const int base = (lbase + lt*16 + g)*BSTR + k0w + tig;
            ah[lt][0] = smw[KHB_W + base];
            ah[lt][1] = smw[KHB_W + base + 8*BSTR];
            ah[lt][2] = smw[KHB_W + base + 4];
            ah[lt][3] = smw[KHB_W + base + 8*BSTR + 4];
            al[lt][0] = smw[KLB_W + base];
            al[lt][1] = smw[KLB_W + base + 8*BSTR];
            al[lt][2] = smw[KLB_W + base + 4];
            al[lt][3] = smw[KLB_W + base + 8*BSTR + 4];
        }
#pragma unroll
        for (int nt = 0; nt < 8; nt++) {
            const int bb = (n0base + nt*8 + g)*BSTR + k0w + tig;
            u32 bh0 = smw[PHB_W + bb];
            u32 bh1 = smw[PHB_W + bb + 4];
            u32 bl0 = smw[PLB_W + bb];
            u32 bl1 = smw[PLB_W + bb + 4];
#pragma unroll
            for (int lt = 0; lt < 2; lt++) {
                mma16(acc[lt][nt], ah[lt], bh0, bh1);
                mma16(acc[lt][nt], ah[lt], bl0, bl1);
                mma16(acc[lt][nt], al[lt], bh0, bh1);
            }
        }
    }
    __syncthreads();   // all warps done reading phase-A operands

    // ---- Epilogue 1: exp, tf32 store TRANSPOSED qpT[m][l], ksum from registers ----
    {
        float sqa[2][2];
#pragma unroll
        for (int lt = 0; lt < 2; lt++) {
            const int r1 = lbase + lt*16 + g;
            sqa[lt][0] = smf[SQN1_F + r1];
            sqa[lt][1] = smf[SQN1_F + r1 + 8];
        }
#pragma unroll
        for (int nt = 0; nt < 8; nt++) {
            const int n = n0base + nt*8 + 2*tig;
            float cs0 = 0.f, cs1 = 0.f;
#pragma unroll
            for (int lt = 0; lt < 2; lt++) {
                const int r1 = lbase + lt*16 + g;
                const int r2 = r1 + 8;
                float e00 = __expf(acc[lt][nt][0] - sqa[lt][0] + EPSK);
                float e01 = __expf(acc[lt][nt][1] - sqa[lt][0] + EPSK);
                float e10 = __expf(acc[lt][nt][2] - sqa[lt][1] + EPSK);
                float e11 = __expf(acc[lt][nt][3] - sqa[lt][1] + EPSK);
                cs0 += e00 + e10;
                cs1 += e01 + e11;
                smf[QPT_F + n*QPT_STR + r1]     = tf32r(e00);
                smf[QPT_F + (n+1)*QPT_STR + r1] = tf32r(e01);
                smf[QPT_F + n*QPT_STR + r2]     = tf32r(e10);
                smf[QPT_F + (n+1)*QPT_STR + r2] = tf32r(e11);
            }
            cs0 += __shfl_xor_sync(0xffffffffu, cs0, 4);
            cs0 += __shfl_xor_sync(0xffffffffu, cs0, 8);
            cs0 += __shfl_xor_sync(0xffffffffu, cs0, 16);
            cs1 += __shfl_xor_sync(0xffffffffu, cs1, 4);
            cs1 += __shfl_xor_sync(0xffffffffu, cs1, 8);
            cs1 += __shfl_xor_sync(0xffffffffu, cs1, 16);
            if (lane < 4) {
                smf[PKS_F + w*64 + nt*8 + 2*tig]     = cs0;
                smf[PKS_F + w*64 + nt*8 + 2*tig + 1] = cs1;
            }
        }
    }
    // ---- load v tile (tf32-rounded) into stride-72 fp32 smem ----
    {
        const float4* src = (const float4*)(vg + gbase + (size_t)l0*D_);
#pragma unroll
        for (int i = 0; i < 4; i++) {
            int id = t + i * NT;               // 2048 float4
            int l = id >> 4, c4 = id & 15;
            float4 x = src[id];
            x.x = tf32r(x.x); x.y = tf32r(x.y); x.z = tf32r(x.z); x.w = tf32r(x.w);
            *(float4*)(smf + V_F + l*VSTR + c4*4) = x;
        }
    }
    __syncthreads();

    // ---- GEMM2 (tf32): kv_partial[256,64] = qpT[256,128] @ v[128,64]; 16 m-rows/warp ----
    const int m0 = w * 16;
    float acc2[8][4];
#pragma unroll
    for (int nt = 0; nt < 8; nt++)
#pragma unroll
        for (int i = 0; i < 4; i++) acc2[nt][i] = 0.f;

    for (int k8 = 0; k8 < 16; k8++) {
        const int lk = k8 * 8;
        u32 a[4];
        a[0] = f2u(smf[QPT_F + (m0+g)*QPT_STR + lk + tig]);
        a[1] = f2u(smf[QPT_F + (m0+8+g)*QPT_STR + lk + tig]);
        a[2] = f2u(smf[QPT_F + (m0+g)*QPT_STR + lk + tig + 4]);
        a[3] = f2u(smf[QPT_F + (m0+8+g)*QPT_STR + lk + tig + 4]);
#pragma unroll
        for (int nt = 0; nt < 8; nt++) {
            u32 b0 = f2u(smf[V_F + (lk+tig)*VSTR + nt*8 + g]);
            u32 b1 = f2u(smf[V_F + (lk+tig+4)*VSTR + nt*8 + g]);
            mma8(acc2[nt], a, b0, b1);
        }
    }

    // ---- write kv partial + ksum partial ----
    float* pb = g_part + (size_t)(bh*CH2 + tile) * PART_SZ;
    {
        const int r1 = m0 + g, r2 = r1 + 8;
#pragma unroll
        for (int nt = 0; nt < 8; nt++) {
            const int d = nt*8 + 2*tig;
            *(float2*)(pb + r1*D_ + d) = make_float2(acc2[nt][0], acc2[nt][1]);
            *(float2*)(pb + r2*D_ + d) = make_float2(acc2[nt][2], acc2[nt][3]);
        }
    }
    if (t < M_) {
        const int wb = (t >> 6) * 4, nloc = t & 63;
        float s = smf[PKS_F + (wb+0)*64 + nloc]
                + smf[PKS_F + (wb+1)*64 + nloc]
                + smf[PKS_F + (wb+2)*64 + nloc]
                + smf[PKS_F + (wb+3)*64 + nloc];
        pb[M_*D_ + t] = s;
    }
}

// ========== reduce: partials -> ksum fp32, kv tf32-rounded fp32 ==========

__global__ void k_reduce() {
    int idx = blockIdx.x * 256 + threadIdx.x;
    int bh = idx / PART_SZ;
    int r  = idx - bh * PART_SZ;
    const float* p = g_part + (size_t)bh * CH2 * PART_SZ + r;
    float s = 0.f;
#pragma unroll
    for (int c = 0; c < CH2; c++) s += p[(size_t)c * PART_SZ];
    if (r < M_*D_) g_kv[bh*M_*D_ + r] = tf32r(s);
    else           g_ksum[bh*M_ + (r - M_*D_)] = s;
}

// ============================ k2: bf16-GEMM1 + tf32-GEMM2 ============================
// phase A (words): QHB@0 (4608), QLB@4608, PHB2@9216 (9216), PLB2@18432 -> 27648
// phase B (fp32): QP@0 (128*260=33280), KV@33280 (256*72=18432) -> 51712
// tail: SQN@51712(128) KSUM@51840(256) ZP@52096(512) TMP@52608(512) -> 53120 floats
#define QHB_W  0
#define QLB_W  4608
#define PHB2_W 9216
#define PLB2_W 18432
#define QP_F   0
#define KV_F   33280
#define SQN_F  51712
#define KSUM_F 51840
#define ZP_F   52096
#define TMP_F  52608
#define K2_FLOATS 53120
#define K2_SMEM (K2_FLOATS*4)
#define QPSTR 260
#define KVSTR 72

__global__ void __launch_bounds__(NT, 1)
k2_out(const float* __restrict__ qg, float* __restrict__ outg) {
    extern __shared__ float smf[];
    u32* smw = (u32*)smf;
    const int t = threadIdx.x;
    const int lane = t & 31, w = t >> 5;      // 16 warps
    const int g = lane >> 2, tig = lane & 3;
    const int bh = blockIdx.x >> 6, tile = blockIdx.x & 63;
    const int l0 = tile * 128;
    const size_t gbase = (size_t)bh * L_ * D_;

    // ---- copy P bf16 hi/lo into stride-36 smem ----
    {
        const uint4* sh = (const uint4*)g_Pbh;
        const uint4* sl = (const uint4*)g_Pbl;
#pragma unroll
        for (int i = 0; i < 4; i++) {
            int id = t + i * NT;
            int m = id >> 3, j = id & 7;
            *(uint4*)(smw + PHB2_W + m*BSTR + j*4) = sh[id];
            *(uint4*)(smw + PLB2_W + m*BSTR + j*4) = sl[id];
        }
    }
    // ---- load q tile, scale, bf16 split, sqn partials ----
    {
        const int r = t >> 2, c0w = (t & 3) * 8;
        const float4* src = (const float4*)(qg + gbase + (size_t)(l0 + r)*D_ + (t & 3)*16);
        float ss = 0.f;
#pragma unroll
        for (int i = 0; i < 4; i++) {
            float4 x = src[i];
            x.x *= NORMV; x.y *= NORMV; x.z *= NORMV; x.w *= NORMV;
            ss += x.x*x.x + x.y*x.y + x.z*x.z + x.w*x.w;
            u32 h01, l01, h23, l23;
            bsplit2(x.x, x.y, h01, l01);
            bsplit2(x.z, x.w, h23, l23);
            *(uint2*)(smw + QHB_W + r*BSTR + c0w + 2*i) = make_uint2(h01, h23);
            *(uint2*)(smw + QLB_W + r*BSTR + c0w + 2*i) = make_uint2(l01, l23);
        }
        smf[TMP_F + t] = ss;
    }
    if (t < M_) smf[KSUM_F + t] = g_ksum[bh*M_ + t];
    __syncthreads();
    if (t < 128) {
        smf[SQN_F + t] = 0.5f * (smf[TMP_F + 4*t] + smf[TMP_F + 4*t+1]
                               + smf[TMP_F + 4*t+2] + smf[TMP_F + 4*t+3]);
    }
    __syncthreads();

    // ---- GEMM1 (bf16 k16): proj[128,256], warp grid 4x4, 3 products ----
    const int lbase = (w & 3) * 32;
    const int n0base = (w >> 2) * 64;
    float acc[2][8][4];
#pragma unroll
    for (int lt = 0; lt < 2; lt++)
#pragma unroll
        for (int nt = 0; nt < 8; nt++)
#pragma unroll
            for (int i = 0; i < 4; i++) acc[lt][nt][i] = 0.f;

#pragma unroll
    for (int ks = 0; ks < 4; ks++) {
        const int k0w = ks * 8;
        u32 ah[2][4], al[2][4];
#pragma unroll
        for (int lt = 0; lt < 2; lt++) {
            const int base = (lbase + lt*16 + g)*BSTR + k0w + tig;
            ah[lt][0] = smw[QHB_W + base];
            ah[lt][1] = smw[QHB_W + base + 8*BSTR];
            ah[lt][2] = smw[QHB_W + base + 4];
            ah[lt][3] = smw[QHB_W + base + 8*BSTR + 4];
            al[lt][0] = smw[QLB_W + base];
            al[lt][1] = smw[QLB_W + base + 8*BSTR];
            al[lt][2] = smw[QLB_W + base + 4];
            al[lt][3] = smw[QLB_W + base + 8*BSTR + 4];
        }
#pragma unroll
        for (int nt = 0; nt < 8; nt++) {
            const int bb = (n0base + nt*8 + g)*BSTR + k0w + tig;
            u32 bh0 = smw[PHB2_W + bb];
            u32 bh1 = smw[PHB2_W + bb + 4];
            u32 bl0 = smw[PLB2_W + bb];
            u32 bl1 = smw[PLB2_W + bb + 4];
#pragma unroll
            for (int lt = 0; lt < 2; lt++) {
                mma16(acc[lt][nt], ah[lt], bh0, bh1);
                mma16(acc[lt][nt], ah[lt], bl0, bl1);
                mma16(acc[lt][nt], al[lt], bh0, bh1);
            }
        }
    }
    __syncthreads();

    // ---- Epilogue 1: exp, z-dot, tf32 round, store q' ----
#pragma unroll
    for (int lt = 0; lt < 2; lt++) {
        const int r1 = lbase + lt*16 + g;
        const int r2 = r1 + 8;
        const float sq1 = smf[SQN_F + r1], sq2 = smf[SQN_F + r2];
        float za1 = 0.f, za2 = 0.f;
#pragma unroll
        for (int nt = 0; nt < 8; nt++) {
            const int n = n0base + nt*8 + 2*tig;
            const float ks0 = smf[KSUM_F + n], ks1 = smf[KSUM_F + n + 1];
            float e00 = __expf(acc[lt][nt][0] - sq1 + EPSK);
            float e01 = __expf(acc[lt][nt][1] - sq1 + EPSK);
            float e10 = __expf(acc[lt][nt][2] - sq2 + EPSK);
            float e11 = __expf(acc[lt][nt][3] - sq2 + EPSK);
            za1 += e00*ks0 + e01*ks1;
            za2 += e10*ks0 + e11*ks1;
            *(float2*)(smf + QP_F + r1*QPSTR + n) = make_float2(tf32r(e00), tf32r(e01));
            *(float2*)(smf + QP_F + r2*QPSTR + n) = make_float2(tf32r(e10), tf32r(e11));
        }
        za1 += __shfl_xor_sync(0xffffffffu, za1, 1);
        za1 += __shfl_xor_sync(0xffffffffu, za1, 2);
        za2 += __shfl_xor_sync(0xffffffffu, za2, 1);
        za2 += __shfl_xor_sync(0xffffffffu, za2, 2);
        if (tig == 0) {
            float* zp = smf + ZP_F + (w >> 2) * 128;
            zp[r1] = za1;
            zp[r2] = za2;
        }
    }
    // ---- load kv (tf32-rounded) into stride-72 fp32 smem ----
    {
        const float4* src = (const float4*)(g_kv + (size_t)bh * M_ * D_);
#pragma unroll
        for (int i = 0; i < 8; i++) {
            int id = t + i * NT;
            int m = id >> 4, c4 = id & 15;
            *(float4*)(smf + KV_F + m*KVSTR + c4*4) = src[id];
        }
    }
    __syncthreads();

    // ---- GEMM2 (tf32): out[128,64] = q'[128,256] @ kv[256,64]; warp grid 8x2 ----
    const int r0 = (w & 7)*16 + g;
    const int colbase = (w >> 3) * 32;
    float acc2[4][4];
#pragma unroll
    for (int nt = 0; nt < 4; nt++)
#pragma unroll
        for (int i = 0; i < 4; i++) acc2[nt][i] = 0.f;

    for (int km = 0; km < 32; km++) {
        const int m0 = km * 8;
        u32 a[4];
        a[0] = f2u(smf[QP_F + r0*QPSTR + m0 + tig]);
        a[1] = f2u(smf[QP_F + (r0+8)*QPSTR + m0 + tig]);
        a[2] = f2u(smf[QP_F + r0*QPSTR + m0 + tig + 4]);
        a[3] = f2u(smf[QP_F + (r0+8)*QPSTR + m0 + tig + 4]);
#pragma unroll
        for (int nt = 0; nt < 4; nt++) {
            u32 b0 = f2u(smf[KV_F + (m0+tig)*KVSTR + colbase + nt*8 + g]);
            u32 b1 = f2u(smf[KV_F + (m0+tig+4)*KVSTR + colbase + nt*8 + g]);
            mma8(acc2[nt], a, b0, b1);
        }
    }

    // ---- Epilogue 2: scale by z (sum of 4 group partials), store ----
    {
        const float* zp = smf + ZP_F;
        const float z1 = 1.0f / (zp[r0] + zp[128 + r0] + zp[256 + r0] + zp[384 + r0] + EPSZ);
        const float z2 = 1.0f / (zp[r0+8] + zp[128 + r0+8] + zp[256 + r0+8] + zp[384 + r0+8] + EPSZ);
        float* o1 = outg + gbase + (size_t)(l0 + r0)*D_ + colbase;
        float* o2 = outg + gbase + (size_t)(l0 + r0 + 8)*D_ + colbase;
#pragma unroll
        for (int nt = 0; nt < 4; nt++) {
            const int d = nt*8 + 2*tig;
            *(float2*)(o1 + d) = make_float2(acc2[nt][0]*z1, acc2[nt][1]*z1);
            *(float2*)(o2 + d) = make_float2(acc2[nt][2]*z2, acc2[nt][3]*z2);
        }
    }
}

extern "C" void kernel_launch(void* const* d_in, const int* in_sizes, int n_in,
                              void* d_out, int out_size) {
    (void)in_sizes; (void)n_in; (void)out_size;
    const float* q = (const float*)d_in[0];
    const float* k = (const float*)d_in[1];
    const float* v = (const float*)d_in[2];
    const float* P = (const float*)d_in[3];
    float* out = (float*)d_out;

    cudaFuncSetAttribute(k1_mma, cudaFuncAttributeMaxDynamicSharedMemorySize, K1_SMEM);
    cudaFuncSetAttribute(k2_out, cudaFuncAttributeMaxDynamicSharedMemorySize, K2_SMEM);

    k_prep_P<<<32, 256>>>(P);
    k1_mma<<<BH_*CH2, NT, K1_SMEM>>>(k, v);
    k_reduce<<<(BH_*PART_SZ)/256, 256>>>();
    k2_out<<<BH_*CH2, NT, K2_SMEM>>>(q, out);
}